// round 2
// baseline (speedup 1.0000x reference)
#include <cuda_runtime.h>
#include <cstdint>
#include <cstddef>
#include <math.h>

static constexpr int Bn = 8;
static constexpr int Sn = 2048;
static constexpr int Dn = 384;
static constexpr int Hn = 6;
static constexpr int DHn = 64;
static constexpr int BSn = Bn * Sn;   // 16384
static constexpr int BHn = Bn * Hn;   // 48

__device__ float g_out [BSn * Dn];
__device__ float g_left[BSn * Dn];
__device__ float g_xc  [BSn * Dn];
__device__ float g_q   [BSn * Dn];
__device__ float g_k   [BSn * Dn];
__device__ float g_v   [BSn * Dn];
__device__ float g_ig  [BSn * Hn];
__device__ float g_fg  [BSn * Hn];
__device__ float g_fe  [BHn * Sn];
__device__ float g_ie  [BHn * Sn];
__device__ float g_rd  [BHn * Sn];
__device__ float g_h   [(size_t)BHn * Sn * DHn];
__device__ float g_prod[BSn * Dn];

__device__ __forceinline__ float warp_sum(float v) {
    #pragma unroll
    for (int o = 16; o > 0; o >>= 1) v += __shfl_xor_sync(0xffffffffu, v, o);
    return v;
}

// 1) LayerNorm, eps = 384
__global__ void ln_kernel(const float* __restrict__ x, const float* __restrict__ g,
                          const float* __restrict__ b, float* __restrict__ out) {
    int w = threadIdx.x >> 5, lane = threadIdx.x & 31;
    int row = blockIdx.x * 4 + w;
    const float* xr = x + (size_t)row * Dn;
    float vals[12];
    #pragma unroll
    for (int p = 0; p < 3; p++) {
        float4 t = *reinterpret_cast<const float4*>(xr + (lane + 32 * p) * 4);
        vals[p*4+0]=t.x; vals[p*4+1]=t.y; vals[p*4+2]=t.z; vals[p*4+3]=t.w;
    }
    float s = 0.f;
    #pragma unroll
    for (int i = 0; i < 12; i++) s += vals[i];
    float mu = warp_sum(s) * (1.0f / Dn);
    float ss = 0.f;
    #pragma unroll
    for (int i = 0; i < 12; i++) { vals[i] -= mu; ss += vals[i]*vals[i]; }
    float rs = rsqrtf(warp_sum(ss) * (1.0f / Dn) + 384.0f);
    float* orow = out + (size_t)row * Dn;
    #pragma unroll
    for (int p = 0; p < 3; p++) {
        int c = (lane + 32 * p) * 4;
        float4 t;
        t.x = vals[p*4+0]*rs*g[c+0]+b[c+0]; t.y = vals[p*4+1]*rs*g[c+1]+b[c+1];
        t.z = vals[p*4+2]*rs*g[c+2]+b[c+2]; t.w = vals[p*4+3]*rs*g[c+3]+b[c+3];
        *reinterpret_cast<float4*>(orow + c) = t;
    }
}

// 2) C[M,N] = (A[M,K] @ W[N,K]^T + bias) * scale (+ addend), optional row flip on store
__global__ void gemm_nt(const float* __restrict__ A, const float* __restrict__ W,
                        const float* __restrict__ bias, float* __restrict__ Cout,
                        const float* __restrict__ addend, float scale,
                        int N, int K, const int* __restrict__ flipPtr) {
    __shared__ float As[128][17];
    __shared__ float Bs[64][17];
    int tid = threadIdx.x;
    int tmIdx = tid >> 4, tnIdx = tid & 15;
    int m0 = blockIdx.x * 128, n0 = blockIdx.y * 64;
    float acc[8][4];
    #pragma unroll
    for (int i = 0; i < 8; i++)
        #pragma unroll
        for (int j = 0; j < 4; j++) acc[i][j] = 0.f;

    for (int k0 = 0; k0 < K; k0 += 16) {
        #pragma unroll
        for (int p = 0; p < 2; p++) {
            int fid = tid + 256 * p;
            int m = fid >> 2, c4 = (fid & 3) * 4;
            float4 av = *reinterpret_cast<const float4*>(A + (size_t)(m0+m)*K + k0 + c4);
            As[m][c4+0]=av.x; As[m][c4+1]=av.y; As[m][c4+2]=av.z; As[m][c4+3]=av.w;
        }
        {
            int n = tid >> 2, c4 = (tid & 3) * 4;
            float4 bv = *reinterpret_cast<const float4*>(W + (size_t)(n0+n)*K + k0 + c4);
            Bs[n][c4+0]=bv.x; Bs[n][c4+1]=bv.y; Bs[n][c4+2]=bv.z; Bs[n][c4+3]=bv.w;
        }
        __syncthreads();
        #pragma unroll
        for (int kk = 0; kk < 16; kk++) {
            float a[8], bb[4];
            #pragma unroll
            for (int i = 0; i < 8; i++) a[i] = As[tmIdx + 16*i][kk];
            #pragma unroll
            for (int j = 0; j < 4; j++) bb[j] = Bs[tnIdx + 16*j][kk];
            #pragma unroll
            for (int i = 0; i < 8; i++)
                #pragma unroll
                for (int j = 0; j < 4; j++) acc[i][j] += a[i] * bb[j];
        }
        __syncthreads();
    }
    int fl = flipPtr ? *flipPtr : 0;
    #pragma unroll
    for (int j = 0; j < 4; j++) {
        int col = n0 + tnIdx + 16 * j;
        float bj = bias[col];
        #pragma unroll
        for (int i = 0; i < 8; i++) {
            int m = m0 + tmIdx + 16 * i;
            float val = (acc[i][j] + bj) * scale;
            if (addend) val += addend[(size_t)m * N + col];
            int ms = m;
            if (fl) { int bb_ = m >> 11, sIdx = m & 2047; ms = (bb_ << 11) + (Sn - 1 - sIdx); }
            Cout[(size_t)ms * N + col] = val;
        }
    }
}

// 3) causal depthwise conv (K=4) + SiLU
__global__ void conv_kernel(const float* __restrict__ left, const float* __restrict__ cw,
                            const float* __restrict__ cb, float* __restrict__ xc) {
    int bt = blockIdx.x;
    int b = bt >> 11, t = bt & 2047;
    #pragma unroll
    for (int p = 0; p < 3; p++) {
        int d = threadIdx.x + 128 * p;
        float acc = cb[d];
        #pragma unroll
        for (int j = 0; j < 4; j++) {
            int tt = t - 3 + j;
            if (tt >= 0) acc += cw[d*4+j] * left[((size_t)b*Sn + tt)*Dn + d];
        }
        xc[(size_t)bt*Dn + d] = acc / (1.0f + expf(-acc));
    }
}

// 4) ig / fg (6 outputs each per row)
__global__ void igfg_kernel(const float* __restrict__ left,
                            const float* __restrict__ Wi, const float* __restrict__ bi,
                            const float* __restrict__ Wf, const float* __restrict__ bf,
                            float* __restrict__ ig, float* __restrict__ fg) {
    __shared__ float Ar[16][385];
    __shared__ float Ws[12][385];
    int tid = threadIdx.x;
    int row0 = blockIdx.x * 16;
    for (int i = tid; i < 16 * Dn; i += 192) {
        int r = i / Dn, kk = i - r * Dn;
        Ar[r][kk] = left[((size_t)row0 + r) * Dn + kk];
    }
    for (int i = tid; i < 12 * Dn; i += 192) {
        int o = i / Dn, kk = i - o * Dn;
        Ws[o][kk] = (o < 6) ? Wi[o*Dn+kk] : Wf[(o-6)*Dn+kk];
    }
    __syncthreads();
    int r = tid / 12, o = tid - r * 12;
    float acc = 0.f;
    #pragma unroll 4
    for (int kk = 0; kk < Dn; kk++) acc += Ar[r][kk] * Ws[o][kk];
    int row = row0 + r;
    if (o < 6) ig[(size_t)row*Hn + o] = acc + bi[o];
    else {
        int h = o - 6;
        float z = acc + bf[h];
        fg[(size_t)row*Hn + h] = fminf(z, 0.f) - log1pf(expf(-fabsf(z)));
    }
}

// 5) gates: closed-form m via (sum,max)-scan; then n-scan + 1/den
__global__ void gates_kernel(const float* __restrict__ ig, const float* __restrict__ fg,
                             const float* __restrict__ k, const float* __restrict__ q,
                             float* __restrict__ fe, float* __restrict__ ie,
                             float* __restrict__ rd) {
    __shared__ float sh[128 * 65];
    float* sF = sh; float* sG = sh + 256; float* oFp = sh + 512; float* pGp = sh + 768;
    int bh = blockIdx.x;
    int b = bh / Hn, h = bh - b * Hn;
    int tid = threadIdx.x; // 256
    float fgl[8], igl[8], Fl[8], Gl[8];
    int tbase = tid * 8;
    #pragma unroll
    for (int j = 0; j < 8; j++) {
        int t = tbase + j;
        fgl[j] = fg[((size_t)b*Sn + t)*Hn + h];
        igl[j] = ig[((size_t)b*Sn + t)*Hn + h];
    }
    float F = 0.f, G = -INFINITY;
    #pragma unroll
    for (int j = 0; j < 8; j++) {
        F += fgl[j]; Fl[j] = F;
        G = fmaxf(G, igl[j] - F); Gl[j] = G;
    }
    sF[tid] = F; sG[tid] = G;
    __syncthreads();
    if (tid == 0) {
        float aF = 0.f, aG = -INFINITY;
        for (int i = 0; i < 256; i++) {
            oFp[i] = aF; pGp[i] = aG;
            aG = fmaxf(aG, sG[i] - aF);
            aF += sF[i];
        }
    }
    __syncthreads();
    float oF = oFp[tid], pG = pGp[tid];
    float mp = oF + pG;
    #pragma unroll
    for (int j = 0; j < 8; j++) {
        float Ft = oF + Fl[j];
        float Gt = fmaxf(pG, Gl[j] - oF);
        float m = Ft + Gt;
        fe[(size_t)bh*Sn + tbase + j] = expf(fgl[j] + mp - m);
        ie[(size_t)bh*Sn + tbase + j] = expf(igl[j] - m);
        mp = m;
    }
    __syncthreads();
    // n-scan + den
    float nreg = 0.f;
    for (int t0 = 0; t0 < Sn; t0 += 128) {
        if (tid < 64) {
            for (int tt = 0; tt < 128; tt++) {
                int t = t0 + tt;
                float fe_ = fe[(size_t)bh*Sn + t];
                float ie_ = ie[(size_t)bh*Sn + t];
                float kv = k[((size_t)b*Sn + t)*Dn + h*DHn + tid];
                nreg = fe_ * nreg + ie_ * kv;
                sh[tt*65 + tid] = nreg;
            }
        }
        __syncthreads();
        if (tid < 128) {
            int t = t0 + tid;
            const float* qr = q + ((size_t)b*Sn + t)*Dn + h*DHn;
            float den = 0.f;
            #pragma unroll 8
            for (int j = 0; j < 64; j++) den += sh[tid*65 + j] * qr[j];
            rd[(size_t)bh*Sn + t] = 1.0f / fmaxf(fabsf(den), 1.0f);
        }
        __syncthreads();
    }
}

// 6) main mLSTM C-scan: 2 blocks per (b,h), 32 v-rows each
static constexpr int Tt = 32;
__global__ void scan_kernel(const float* __restrict__ q, const float* __restrict__ k,
                            const float* __restrict__ v,
                            const float* __restrict__ fe, const float* __restrict__ ie,
                            const float* __restrict__ rd, float* __restrict__ hout) {
    __shared__ float qs[Tt][64], ks[Tt][64], vs[Tt][32];
    __shared__ float fes[Tt], ies[Tt], rds[Tt];
    __shared__ float hs[Tt][32];
    int bh = blockIdx.x >> 1;
    int half = blockIdx.x & 1;
    int b = bh / Hn, h = bh - b * Hn;
    int tid = threadIdx.x;       // 128
    int rl = tid >> 2, c = tid & 3;
    const size_t base_qk = (size_t)b*Sn*Dn + h*DHn;
    const size_t base_v  = base_qk + half*32;
    const size_t gbase   = (size_t)bh*Sn;
    float C[16];
    #pragma unroll
    for (int j = 0; j < 16; j++) C[j] = 0.f;

    auto load_tile = [&](int t0) {
        #pragma unroll
        for (int p = 0; p < 4; p++) {
            int fid = tid + 128*p;
            int tt = fid >> 4, j4 = (fid & 15) << 2;
            *reinterpret_cast<float4*>(&qs[tt][j4]) =
                *reinterpret_cast<const float4*>(q + base_qk + (size_t)(t0+tt)*Dn + j4);
            *reinterpret_cast<float4*>(&ks[tt][j4]) =
                *reinterpret_cast<const float4*>(k + base_qk + (size_t)(t0+tt)*Dn + j4);
        }
        #pragma unroll
        for (int p = 0; p < 2; p++) {
            int fid = tid + 128*p;
            int tt = fid >> 3, j4 = (fid & 7) << 2;
            *reinterpret_cast<float4*>(&vs[tt][j4]) =
                *reinterpret_cast<const float4*>(v + base_v + (size_t)(t0+tt)*Dn + j4);
        }
        if (tid < 32)      fes[tid]    = fe[gbase + t0 + tid];
        else if (tid < 64) ies[tid-32] = ie[gbase + t0 + tid - 32];
        else if (tid < 96) rds[tid-64] = rd[gbase + t0 + tid - 64];
    };

    load_tile(0);
    __syncthreads();
    for (int ti = 0; ti < Sn / Tt; ti++) {
        int t0 = ti * Tt;
        #pragma unroll 2
        for (int tt = 0; tt < Tt; tt++) {
            float fet = fes[tt], iet = ies[tt];
            float iv = iet * vs[tt][rl];
            const float4* q4 = reinterpret_cast<const float4*>(&qs[tt][c*16]);
            const float4* k4 = reinterpret_cast<const float4*>(&ks[tt][c*16]);
            float n0=0.f, n1=0.f, n2=0.f, n3=0.f;
            #pragma unroll
            for (int jj = 0; jj < 4; jj++) {
                float4 kk4 = k4[jj];
                float4 qq4 = q4[jj];
                float* Cp = &C[jj*4];
                Cp[0] = fet*Cp[0] + iv*kk4.x; n0 += Cp[0]*qq4.x;
                Cp[1] = fet*Cp[1] + iv*kk4.y; n1 += Cp[1]*qq4.y;
                Cp[2] = fet*Cp[2] + iv*kk4.z; n2 += Cp[2]*qq4.z;
                Cp[3] = fet*Cp[3] + iv*kk4.w; n3 += Cp[3]*qq4.w;
            }
            float num = (n0+n1) + (n2+n3);
            num += __shfl_xor_sync(0xffffffffu, num, 1);
            num += __shfl_xor_sync(0xffffffffu, num, 2);
            if (c == 0) hs[tt][rl] = num * rds[tt];
        }
        __syncthreads();
        #pragma unroll
        for (int p = 0; p < 8; p++) {
            int fid = tid + 128*p;
            int tt = fid >> 5, rr = fid & 31;
            hout[((size_t)bh*Sn + t0 + tt)*DHn + half*32 + rr] = hs[tt][rr];
        }
        if (ti + 1 < Sn / Tt) load_tile(t0 + Tt);
        __syncthreads();
    }
}

// 7) GroupNorm + unflip + multiply by LN out
__global__ void gnprod_kernel(const float* __restrict__ hin,
                              const float* __restrict__ gn_g, const float* __restrict__ gn_b,
                              const float* __restrict__ outln,
                              const int* __restrict__ flipPtr,
                              float* __restrict__ prod) {
    int w = threadIdx.x >> 5, lane = threadIdx.x & 31;
    int u = blockIdx.x * 8 + w;
    int b = u / (Hn * Sn);
    int rem = u - b * (Hn * Sn);
    int h = rem / Sn, t = rem - h * Sn;
    float v0 = hin[(size_t)u*DHn + lane];
    float v1 = hin[(size_t)u*DHn + 32 + lane];
    float mu = warp_sum(v0 + v1) * (1.0f / DHn);
    float x0 = v0 - mu, x1 = v1 - mu;
    float rs = rsqrtf(warp_sum(x0*x0 + x1*x1) * (1.0f / DHn) + 1e-5f);
    int d0 = h*DHn + lane, d1 = d0 + 32;
    float hn0 = x0*rs*gn_g[d0] + gn_b[d0];
    float hn1 = x1*rs*gn_g[d1] + gn_b[d1];
    int s = (*flipPtr) ? (Sn - 1 - t) : t;
    size_t row = ((size_t)b*Sn + s) * Dn;
    prod[row + d0] = hn0 * outln[row + d0];
    prod[row + d1] = hn1 * outln[row + d1];
}

extern "C" void kernel_launch(void* const* d_in, const int* in_sizes, int n_in,
                              void* d_out, int out_size) {
    const float* x    = (const float*)d_in[0];
    const float* ln_g = (const float*)d_in[1];
    const float* ln_b = (const float*)d_in[2];
    const float* W2   = (const float*)d_in[5];
    const float* b2   = (const float*)d_in[6];
    const float* W3   = (const float*)d_in[7];
    const float* b3   = (const float*)d_in[8];
    const float* cw   = (const float*)d_in[9];
    const float* cb   = (const float*)d_in[10];
    const float* Wq   = (const float*)d_in[11];
    const float* bq   = (const float*)d_in[12];
    const float* Wk   = (const float*)d_in[13];
    const float* bk   = (const float*)d_in[14];
    const float* Wv   = (const float*)d_in[15];
    const float* bv   = (const float*)d_in[16];
    const float* Wi   = (const float*)d_in[17];
    const float* bi   = (const float*)d_in[18];
    const float* Wf   = (const float*)d_in[19];
    const float* bf   = (const float*)d_in[20];
    const float* gn_g = (const float*)d_in[21];
    const float* gn_b = (const float*)d_in[22];
    const int*   flip = (const int*)d_in[23];
    float* out = (float*)d_out;

    float *p_out, *p_left, *p_xc, *p_q, *p_k, *p_v, *p_ig, *p_fg,
          *p_fe, *p_ie, *p_rd, *p_h, *p_prod;
    cudaGetSymbolAddress((void**)&p_out,  g_out);
    cudaGetSymbolAddress((void**)&p_left, g_left);
    cudaGetSymbolAddress((void**)&p_xc,   g_xc);
    cudaGetSymbolAddress((void**)&p_q,    g_q);
    cudaGetSymbolAddress((void**)&p_k,    g_k);
    cudaGetSymbolAddress((void**)&p_v,    g_v);
    cudaGetSymbolAddress((void**)&p_ig,   g_ig);
    cudaGetSymbolAddress((void**)&p_fg,   g_fg);
    cudaGetSymbolAddress((void**)&p_fe,   g_fe);
    cudaGetSymbolAddress((void**)&p_ie,   g_ie);
    cudaGetSymbolAddress((void**)&p_rd,   g_rd);
    cudaGetSymbolAddress((void**)&p_h,    g_h);
    cudaGetSymbolAddress((void**)&p_prod, g_prod);

    dim3 ggrid(BSn / 128, Dn / 64);

    ln_kernel<<<BSn / 4, 128>>>(x, ln_g, ln_b, p_out);
    gemm_nt<<<ggrid, 256>>>(p_out, W2, b2, p_left, nullptr, 1.0f, Dn, Dn, flip);
    conv_kernel<<<BSn, 128>>>(p_left, cw, cb, p_xc);
    gemm_nt<<<ggrid, 256>>>(p_xc,   Wq, bq, p_q, nullptr, 1.0f,    Dn, Dn, nullptr);
    gemm_nt<<<ggrid, 256>>>(p_xc,   Wk, bk, p_k, nullptr, 0.125f,  Dn, Dn, nullptr);
    gemm_nt<<<ggrid, 256>>>(p_left, Wv, bv, p_v, nullptr, 1.0f,    Dn, Dn, nullptr);
    igfg_kernel<<<BSn / 16, 192>>>(p_left, Wi, bi, Wf, bf, p_ig, p_fg);
    gates_kernel<<<BHn, 256>>>(p_ig, p_fg, p_k, p_q, p_fe, p_ie, p_rd);
    scan_kernel<<<BHn * 2, 128>>>(p_q, p_k, p_v, p_fe, p_ie, p_rd, p_h);
    gnprod_kernel<<<(BHn * Sn) / 8, 256>>>(p_h, gn_g, gn_b, p_out, flip, p_prod);
    gemm_nt<<<ggrid, 256>>>(p_prod, W3, b3, out, x, 1.0f, Dn, Dn, nullptr);
}

// round 3
// speedup vs baseline: 1.7003x; 1.7003x over previous
#include <cuda_runtime.h>
#include <cstdint>
#include <cstddef>
#include <math.h>

static constexpr int Bn = 8;
static constexpr int Sn = 2048;
static constexpr int Dn = 384;
static constexpr int Hn = 6;
static constexpr int DHn = 64;
static constexpr int BSn = Bn * Sn;   // 16384
static constexpr int BHn = Bn * Hn;   // 48

__device__ float g_out [BSn * Dn];
__device__ float g_left[BSn * Dn];
__device__ float g_xc  [BSn * Dn];
__device__ float g_q   [BSn * Dn];
__device__ float g_k   [BSn * Dn];
__device__ float g_v   [BSn * Dn];
__device__ float g_ig  [BSn * Hn];
__device__ float g_fg  [BSn * Hn];
__device__ float g_fe  [BHn * Sn];
__device__ float g_ie  [BHn * Sn];
__device__ float g_rd  [BHn * Sn];
__device__ float g_h   [(size_t)BHn * Sn * DHn];
__device__ float g_prod[BSn * Dn];

__device__ __forceinline__ float warp_sum(float v) {
    #pragma unroll
    for (int o = 16; o > 0; o >>= 1) v += __shfl_xor_sync(0xffffffffu, v, o);
    return v;
}

__device__ __forceinline__ float cvt_tf32(float x) {
    uint32_t o;
    asm("cvt.rna.tf32.f32 %0, %1;" : "=r"(o) : "f"(x));
    return __uint_as_float(o);
}

// 1) LayerNorm, eps = 384
__global__ void ln_kernel(const float* __restrict__ x, const float* __restrict__ g,
                          const float* __restrict__ b, float* __restrict__ out) {
    int w = threadIdx.x >> 5, lane = threadIdx.x & 31;
    int row = blockIdx.x * 4 + w;
    const float* xr = x + (size_t)row * Dn;
    float vals[12];
    #pragma unroll
    for (int p = 0; p < 3; p++) {
        float4 t = *reinterpret_cast<const float4*>(xr + (lane + 32 * p) * 4);
        vals[p*4+0]=t.x; vals[p*4+1]=t.y; vals[p*4+2]=t.z; vals[p*4+3]=t.w;
    }
    float s = 0.f;
    #pragma unroll
    for (int i = 0; i < 12; i++) s += vals[i];
    float mu = warp_sum(s) * (1.0f / Dn);
    float ss = 0.f;
    #pragma unroll
    for (int i = 0; i < 12; i++) { vals[i] -= mu; ss += vals[i]*vals[i]; }
    float rs = rsqrtf(warp_sum(ss) * (1.0f / Dn) + 384.0f);
    float* orow = out + (size_t)row * Dn;
    #pragma unroll
    for (int p = 0; p < 3; p++) {
        int c = (lane + 32 * p) * 4;
        float4 t;
        t.x = vals[p*4+0]*rs*g[c+0]+b[c+0]; t.y = vals[p*4+1]*rs*g[c+1]+b[c+1];
        t.z = vals[p*4+2]*rs*g[c+2]+b[c+2]; t.w = vals[p*4+3]*rs*g[c+3]+b[c+3];
        *reinterpret_cast<float4*>(orow + c) = t;
    }
}

// 2) tf32 tensor-core GEMM: C[M,384] = (A[M,384] @ W[384,384]^T + bias)*scale (+addend)
//    optional batch-wise sequence flip on store. BM=128 BN=64 BK=32, 8 warps.
__global__ void gemm_tf32(const float* __restrict__ A, const float* __restrict__ W,
                          const float* __restrict__ bias, float* __restrict__ Cout,
                          const float* __restrict__ addend, float scale,
                          const int* __restrict__ flipPtr) {
    constexpr int K = 384, N = 384;
    __shared__ float As[128][36];
    __shared__ float Bs[64][36];
    int tid = threadIdx.x;
    int lane = tid & 31, wid = tid >> 5;
    int warp_m = wid & 3, warp_n = wid >> 2;
    int m0 = blockIdx.x * 128, n0 = blockIdx.y * 64;
    int gq = lane >> 2, tg = lane & 3;

    float acc[2][4][4];
    #pragma unroll
    for (int a = 0; a < 2; a++)
        #pragma unroll
        for (int b = 0; b < 4; b++)
            #pragma unroll
            for (int c = 0; c < 4; c++) acc[a][b][c] = 0.f;

    int ldrow = tid >> 3;
    int ldcol = (tid & 7) * 4;

    for (int k0 = 0; k0 < K; k0 += 32) {
        #pragma unroll
        for (int i = 0; i < 4; i++) {
            int m = ldrow + 32 * i;
            float4 v = *reinterpret_cast<const float4*>(A + (size_t)(m0+m)*K + k0 + ldcol);
            As[m][ldcol+0] = cvt_tf32(v.x); As[m][ldcol+1] = cvt_tf32(v.y);
            As[m][ldcol+2] = cvt_tf32(v.z); As[m][ldcol+3] = cvt_tf32(v.w);
        }
        #pragma unroll
        for (int i = 0; i < 2; i++) {
            int n = ldrow + 32 * i;
            float4 v = *reinterpret_cast<const float4*>(W + (size_t)(n0+n)*K + k0 + ldcol);
            Bs[n][ldcol+0] = cvt_tf32(v.x); Bs[n][ldcol+1] = cvt_tf32(v.y);
            Bs[n][ldcol+2] = cvt_tf32(v.z); Bs[n][ldcol+3] = cvt_tf32(v.w);
        }
        __syncthreads();
        #pragma unroll
        for (int kk = 0; kk < 32; kk += 8) {
            uint32_t af[2][4], bfr[4][2];
            #pragma unroll
            for (int mt = 0; mt < 2; mt++) {
                int mr = warp_m * 32 + mt * 16 + gq;
                af[mt][0] = __float_as_uint(As[mr    ][kk + tg]);
                af[mt][1] = __float_as_uint(As[mr + 8][kk + tg]);
                af[mt][2] = __float_as_uint(As[mr    ][kk + 4 + tg]);
                af[mt][3] = __float_as_uint(As[mr + 8][kk + 4 + tg]);
            }
            #pragma unroll
            for (int nt = 0; nt < 4; nt++) {
                int nr = warp_n * 32 + nt * 8 + gq;
                bfr[nt][0] = __float_as_uint(Bs[nr][kk + tg]);
                bfr[nt][1] = __float_as_uint(Bs[nr][kk + 4 + tg]);
            }
            #pragma unroll
            for (int mt = 0; mt < 2; mt++)
                #pragma unroll
                for (int nt = 0; nt < 4; nt++) {
                    float* d = acc[mt][nt];
                    asm volatile(
                        "mma.sync.aligned.m16n8k8.row.col.f32.tf32.tf32.f32 "
                        "{%0,%1,%2,%3}, {%4,%5,%6,%7}, {%8,%9}, {%0,%1,%2,%3};"
                        : "+f"(d[0]), "+f"(d[1]), "+f"(d[2]), "+f"(d[3])
                        : "r"(af[mt][0]), "r"(af[mt][1]), "r"(af[mt][2]), "r"(af[mt][3]),
                          "r"(bfr[nt][0]), "r"(bfr[nt][1]));
                }
        }
        __syncthreads();
    }

    int fl = flipPtr ? *flipPtr : 0;
    #pragma unroll
    for (int mt = 0; mt < 2; mt++) {
        int r0 = m0 + warp_m * 32 + mt * 16 + gq;
        int r1 = r0 + 8;
        #pragma unroll
        for (int nt = 0; nt < 4; nt++) {
            int col = n0 + warp_n * 32 + nt * 8 + tg * 2;
            float b0v = bias[col], b1v = bias[col + 1];
            float v00 = (acc[mt][nt][0] + b0v) * scale;
            float v01 = (acc[mt][nt][1] + b1v) * scale;
            float v10 = (acc[mt][nt][2] + b0v) * scale;
            float v11 = (acc[mt][nt][3] + b1v) * scale;
            if (addend) {
                v00 += addend[(size_t)r0 * N + col];
                v01 += addend[(size_t)r0 * N + col + 1];
                v10 += addend[(size_t)r1 * N + col];
                v11 += addend[(size_t)r1 * N + col + 1];
            }
            int ms0 = r0, ms1 = r1;
            if (fl) {
                ms0 = (r0 & ~2047) + (Sn - 1 - (r0 & 2047));
                ms1 = (r1 & ~2047) + (Sn - 1 - (r1 & 2047));
            }
            float2 p0 = make_float2(v00, v01);
            float2 p1 = make_float2(v10, v11);
            *reinterpret_cast<float2*>(Cout + (size_t)ms0 * N + col) = p0;
            *reinterpret_cast<float2*>(Cout + (size_t)ms1 * N + col) = p1;
        }
    }
}

// 3) causal depthwise conv (K=4) + SiLU
__global__ void conv_kernel(const float* __restrict__ left, const float* __restrict__ cw,
                            const float* __restrict__ cb, float* __restrict__ xc) {
    int bt = blockIdx.x;
    int b = bt >> 11, t = bt & 2047;
    #pragma unroll
    for (int p = 0; p < 3; p++) {
        int d = threadIdx.x + 128 * p;
        float acc = cb[d];
        #pragma unroll
        for (int j = 0; j < 4; j++) {
            int tt = t - 3 + j;
            if (tt >= 0) acc += cw[d*4+j] * left[((size_t)b*Sn + tt)*Dn + d];
        }
        xc[(size_t)bt*Dn + d] = acc / (1.0f + expf(-acc));
    }
}

// 4) ig / fg
__global__ void igfg_kernel(const float* __restrict__ left,
                            const float* __restrict__ Wi, const float* __restrict__ bi,
                            const float* __restrict__ Wf, const float* __restrict__ bf,
                            float* __restrict__ ig, float* __restrict__ fg) {
    __shared__ float Ar[16][385];
    __shared__ float Ws[12][385];
    int tid = threadIdx.x;
    int row0 = blockIdx.x * 16;
    for (int i = tid; i < 16 * Dn; i += 192) {
        int r = i / Dn, kk = i - r * Dn;
        Ar[r][kk] = left[((size_t)row0 + r) * Dn + kk];
    }
    for (int i = tid; i < 12 * Dn; i += 192) {
        int o = i / Dn, kk = i - o * Dn;
        Ws[o][kk] = (o < 6) ? Wi[o*Dn+kk] : Wf[(o-6)*Dn+kk];
    }
    __syncthreads();
    int r = tid / 12, o = tid - r * 12;
    float acc = 0.f;
    #pragma unroll 4
    for (int kk = 0; kk < Dn; kk++) acc += Ar[r][kk] * Ws[o][kk];
    int row = row0 + r;
    if (o < 6) ig[(size_t)row*Hn + o] = acc + bi[o];
    else {
        int h = o - 6;
        float z = acc + bf[h];
        fg[(size_t)row*Hn + h] = fminf(z, 0.f) - log1pf(expf(-fabsf(z)));
    }
}

// 5) gates: closed-form m; then smem-staged n-scan + 1/den
__global__ void gates_kernel(const float* __restrict__ ig, const float* __restrict__ fg,
                             const float* __restrict__ k, const float* __restrict__ q,
                             float* __restrict__ fe, float* __restrict__ ie,
                             float* __restrict__ rd) {
    __shared__ float sh[128 * 65 + 256];
    float* kbuf = sh;
    float* fes  = sh + 128 * 65;
    float* ies  = fes + 128;
    float* sF = sh; float* sG = sh + 256; float* oFp = sh + 512; float* pGp = sh + 768;

    int bh = blockIdx.x;
    int b = bh / Hn, h = bh - b * Hn;
    int tid = threadIdx.x; // 256
    const size_t gbase = (size_t)bh * Sn;

    // phase 1: m closed form
    float fgl[8], igl[8], Fl[8], Gl[8];
    int tbase = tid * 8;
    #pragma unroll
    for (int j = 0; j < 8; j++) {
        int t = tbase + j;
        fgl[j] = fg[((size_t)b*Sn + t)*Hn + h];
        igl[j] = ig[((size_t)b*Sn + t)*Hn + h];
    }
    float F = 0.f, G = -INFINITY;
    #pragma unroll
    for (int j = 0; j < 8; j++) {
        F += fgl[j]; Fl[j] = F;
        G = fmaxf(G, igl[j] - F); Gl[j] = G;
    }
    sF[tid] = F; sG[tid] = G;
    __syncthreads();
    if (tid == 0) {
        float aF = 0.f, aG = -INFINITY;
        for (int i = 0; i < 256; i++) {
            oFp[i] = aF; pGp[i] = aG;
            aG = fmaxf(aG, sG[i] - aF);
            aF += sF[i];
        }
    }
    __syncthreads();
    float oF = oFp[tid], pG = pGp[tid];
    float mp = oF + pG;
    #pragma unroll
    for (int j = 0; j < 8; j++) {
        float Ft = oF + Fl[j];
        float Gt = fmaxf(pG, Gl[j] - oF);
        float m = Ft + Gt;
        fe[gbase + tbase + j] = expf(fgl[j] + mp - m);
        ie[gbase + tbase + j] = expf(igl[j] - m);
        mp = m;
    }
    __syncthreads();

    // phase 2: n-scan + den, smem-staged
    float nreg = 0.f;
    for (int t0 = 0; t0 < Sn; t0 += 128) {
        for (int idx = tid; idx < 128 * 64; idx += 256) {
            int tt = idx >> 6, j = idx & 63;
            kbuf[tt*65 + j] = k[((size_t)b*Sn + t0 + tt)*Dn + h*DHn + j];
        }
        if (tid < 128) fes[tid] = fe[gbase + t0 + tid];
        else           ies[tid - 128] = ie[gbase + t0 + tid - 128];
        __syncthreads();
        if (tid < 64) {
            #pragma unroll 4
            for (int tt = 0; tt < 128; tt++) {
                nreg = fes[tt] * nreg + ies[tt] * kbuf[tt*65 + tid];
                kbuf[tt*65 + tid] = nreg;
            }
        }
        __syncthreads();
        if (tid < 128) {
            int t = t0 + tid;
            const float* qr = q + ((size_t)b*Sn + t)*Dn + h*DHn;
            float den = 0.f;
            #pragma unroll 8
            for (int j = 0; j < 64; j++) den += kbuf[tid*65 + j] * qr[j];
            rd[gbase + t] = 1.0f / fmaxf(fabsf(den), 1.0f);
        }
        __syncthreads();
    }
}

// 6) main mLSTM C-scan: 4 blocks per (b,h), 16 v-rows each, 128 threads
static constexpr int Tt = 32;
__global__ void scan_kernel(const float* __restrict__ q, const float* __restrict__ k,
                            const float* __restrict__ v,
                            const float* __restrict__ fe, const float* __restrict__ ie,
                            const float* __restrict__ rd, float* __restrict__ hout) {
    __shared__ float qs[Tt][64], ks[Tt][64], vs[Tt][16];
    __shared__ float fes[Tt], ies[Tt], rds[Tt];
    __shared__ float hs[Tt][16];
    int bh = blockIdx.x >> 2;
    int quarter = blockIdx.x & 3;
    int b = bh / Hn, h = bh - b * Hn;
    int tid = threadIdx.x;       // 128
    int rl = tid >> 3;           // 0..15 (v-row within quarter)
    int c = tid & 7;             // 0..7  (8 k-cols each)
    const size_t base_qk = (size_t)b*Sn*Dn + h*DHn;
    const size_t base_v  = base_qk + quarter*16;
    const size_t gbase   = (size_t)bh*Sn;
    float C[8];
    #pragma unroll
    for (int j = 0; j < 8; j++) C[j] = 0.f;

    auto load_tile = [&](int t0) {
        #pragma unroll
        for (int p = 0; p < 4; p++) {
            int fid = tid + 128*p;
            int tt = fid >> 4, j4 = (fid & 15) << 2;
            *reinterpret_cast<float4*>(&qs[tt][j4]) =
                *reinterpret_cast<const float4*>(q + base_qk + (size_t)(t0+tt)*Dn + j4);
            *reinterpret_cast<float4*>(&ks[tt][j4]) =
                *reinterpret_cast<const float4*>(k + base_qk + (size_t)(t0+tt)*Dn + j4);
        }
        {
            int tt = tid >> 2, j4 = (tid & 3) << 2;
            *reinterpret_cast<float4*>(&vs[tt][j4]) =
                *reinterpret_cast<const float4*>(v + base_v + (size_t)(t0+tt)*Dn + j4);
        }
        if (tid < 32)      fes[tid]    = fe[gbase + t0 + tid];
        else if (tid < 64) ies[tid-32] = ie[gbase + t0 + tid - 32];
        else if (tid < 96) rds[tid-64] = rd[gbase + t0 + tid - 64];
    };

    load_tile(0);
    __syncthreads();
    for (int ti = 0; ti < Sn / Tt; ti++) {
        int t0 = ti * Tt;
        #pragma unroll 2
        for (int tt = 0; tt < Tt; tt++) {
            float fet = fes[tt];
            float iv = ies[tt] * vs[tt][rl];
            const float4* q4 = reinterpret_cast<const float4*>(&qs[tt][c*8]);
            const float4* k4 = reinterpret_cast<const float4*>(&ks[tt][c*8]);
            float n0=0.f, n1=0.f;
            #pragma unroll
            for (int jj = 0; jj < 2; jj++) {
                float4 kk4 = k4[jj];
                float4 qq4 = q4[jj];
                float* Cp = &C[jj*4];
                Cp[0] = fet*Cp[0] + iv*kk4.x; n0 += Cp[0]*qq4.x;
                Cp[1] = fet*Cp[1] + iv*kk4.y; n1 += Cp[1]*qq4.y;
                Cp[2] = fet*Cp[2] + iv*kk4.z; n0 += Cp[2]*qq4.z;
                Cp[3] = fet*Cp[3] + iv*kk4.w; n1 += Cp[3]*qq4.w;
            }
            float num = n0 + n1;
            num += __shfl_xor_sync(0xffffffffu, num, 1);
            num += __shfl_xor_sync(0xffffffffu, num, 2);
            num += __shfl_xor_sync(0xffffffffu, num, 4);
            if (c == 0) hs[tt][rl] = num * rds[tt];
        }
        __syncthreads();
        #pragma unroll
        for (int p = 0; p < 4; p++) {
            int fid = tid + 128*p;
            int tt = fid >> 4, rr = fid & 15;
            hout[((size_t)bh*Sn + t0 + tt)*DHn + quarter*16 + rr] = hs[tt][rr];
        }
        if (ti + 1 < Sn / Tt) load_tile(t0 + Tt);
        __syncthreads();
    }
}

// 7) GroupNorm + unflip + multiply by LN out
__global__ void gnprod_kernel(const float* __restrict__ hin,
                              const float* __restrict__ gn_g, const float* __restrict__ gn_b,
                              const float* __restrict__ outln,
                              const int* __restrict__ flipPtr,
                              float* __restrict__ prod) {
    int w = threadIdx.x >> 5, lane = threadIdx.x & 31;
    int u = blockIdx.x * 8 + w;
    int b = u / (Hn * Sn);
    int rem = u - b * (Hn * Sn);
    int h = rem / Sn, t = rem - h * Sn;
    float v0 = hin[(size_t)u*DHn + lane];
    float v1 = hin[(size_t)u*DHn + 32 + lane];
    float mu = warp_sum(v0 + v1) * (1.0f / DHn);
    float x0 = v0 - mu, x1 = v1 - mu;
    float rs = rsqrtf(warp_sum(x0*x0 + x1*x1) * (1.0f / DHn) + 1e-5f);
    int d0 = h*DHn + lane, d1 = d0 + 32;
    float hn0 = x0*rs*gn_g[d0] + gn_b[d0];
    float hn1 = x1*rs*gn_g[d1] + gn_b[d1];
    int s = (*flipPtr) ? (Sn - 1 - t) : t;
    size_t row = ((size_t)b*Sn + s) * Dn;
    prod[row + d0] = hn0 * outln[row + d0];
    prod[row + d1] = hn1 * outln[row + d1];
}

extern "C" void kernel_launch(void* const* d_in, const int* in_sizes, int n_in,
                              void* d_out, int out_size) {
    const float* x    = (const float*)d_in[0];
    const float* ln_g = (const float*)d_in[1];
    const float* ln_b = (const float*)d_in[2];
    const float* W2   = (const float*)d_in[5];
    const float* b2   = (const float*)d_in[6];
    const float* W3   = (const float*)d_in[7];
    const float* b3   = (const float*)d_in[8];
    const float* cw   = (const float*)d_in[9];
    const float* cb   = (const float*)d_in[10];
    const float* Wq   = (const float*)d_in[11];
    const float* bq   = (const float*)d_in[12];
    const float* Wk   = (const float*)d_in[13];
    const float* bk   = (const float*)d_in[14];
    const float* Wv   = (const float*)d_in[15];
    const float* bv   = (const float*)d_in[16];
    const float* Wi   = (const float*)d_in[17];
    const float* bi   = (const float*)d_in[18];
    const float* Wf   = (const float*)d_in[19];
    const float* bf   = (const float*)d_in[20];
    const float* gn_g = (const float*)d_in[21];
    const float* gn_b = (const float*)d_in[22];
    const int*   flip = (const int*)d_in[23];
    float* out = (float*)d_out;

    float *p_out, *p_left, *p_xc, *p_q, *p_k, *p_v, *p_ig, *p_fg,
          *p_fe, *p_ie, *p_rd, *p_h, *p_prod;
    cudaGetSymbolAddress((void**)&p_out,  g_out);
    cudaGetSymbolAddress((void**)&p_left, g_left);
    cudaGetSymbolAddress((void**)&p_xc,   g_xc);
    cudaGetSymbolAddress((void**)&p_q,    g_q);
    cudaGetSymbolAddress((void**)&p_k,    g_k);
    cudaGetSymbolAddress((void**)&p_v,    g_v);
    cudaGetSymbolAddress((void**)&p_ig,   g_ig);
    cudaGetSymbolAddress((void**)&p_fg,   g_fg);
    cudaGetSymbolAddress((void**)&p_fe,   g_fe);
    cudaGetSymbolAddress((void**)&p_ie,   g_ie);
    cudaGetSymbolAddress((void**)&p_rd,   g_rd);
    cudaGetSymbolAddress((void**)&p_h,    g_h);
    cudaGetSymbolAddress((void**)&p_prod, g_prod);

    dim3 ggrid(BSn / 128, Dn / 64);

    ln_kernel<<<BSn / 4, 128>>>(x, ln_g, ln_b, p_out);
    gemm_tf32<<<ggrid, 256>>>(p_out, W2, b2, p_left, nullptr, 1.0f, flip);
    conv_kernel<<<BSn, 128>>>(p_left, cw, cb, p_xc);
    gemm_tf32<<<ggrid, 256>>>(p_xc,   Wq, bq, p_q, nullptr, 1.0f,   nullptr);
    gemm_tf32<<<ggrid, 256>>>(p_xc,   Wk, bk, p_k, nullptr, 0.125f, nullptr);
    gemm_tf32<<<ggrid, 256>>>(p_left, Wv, bv, p_v, nullptr, 1.0f,   nullptr);
    igfg_kernel<<<BSn / 16, 192>>>(p_left, Wi, bi, Wf, bf, p_ig, p_fg);
    gates_kernel<<<BHn, 256>>>(p_ig, p_fg, p_k, p_q, p_fe, p_ie, p_rd);
    scan_kernel<<<BHn * 4, 128>>>(p_q, p_k, p_v, p_fe, p_ie, p_rd, p_h);
    gnprod_kernel<<<(BHn * Sn) / 8, 256>>>(p_h, gn_g, gn_b, p_out, flip, p_prod);
    gemm_tf32<<<ggrid, 256>>>(p_prod, W3, b3, out, x, 1.0f, nullptr);
}

// round 7
// speedup vs baseline: 2.5439x; 1.4962x over previous
#include <cuda_runtime.h>
#include <cstdint>
#include <cstddef>
#include <math.h>

static constexpr int Bn = 8;
static constexpr int Sn = 2048;
static constexpr int Dn = 384;
static constexpr int Hn = 6;
static constexpr int DHn = 64;
static constexpr int BSn = Bn * Sn;   // 16384
static constexpr int BHn = Bn * Hn;   // 48
static constexpr int NC = Sn / 64;    // 32 chunks

__device__ float g_out [BSn * Dn];
__device__ float g_left[BSn * Dn];
__device__ float g_xc  [BSn * Dn];
__device__ float g_q   [BSn * Dn];
__device__ float g_k   [BSn * Dn];
__device__ float g_v   [BSn * Dn];
__device__ float g_ig  [BSn * Hn];
__device__ float g_fg  [BSn * Hn];
__device__ float g_fe  [BHn * Sn];
__device__ float g_ie  [BHn * Sn];
__device__ float g_m   [BHn * Sn];
__device__ float g_rd  [BHn * Sn];
__device__ float g_h   [(size_t)BHn * Sn * DHn];
__device__ float g_G   [(size_t)BHn * NC * DHn * DHn];
__device__ float g_SC  [BHn * NC * 4];
__device__ float g_prod[BSn * Dn];

__device__ __forceinline__ float warp_sum(float v) {
    #pragma unroll
    for (int o = 16; o > 0; o >>= 1) v += __shfl_xor_sync(0xffffffffu, v, o);
    return v;
}
__device__ __forceinline__ float cvt_tf32(float x) {
    uint32_t o;
    asm("cvt.rna.tf32.f32 %0, %1;" : "=r"(o) : "f"(x));
    return __uint_as_float(o);
}
__device__ __forceinline__ void mma_tf32(float* d, const uint32_t* a, const uint32_t* b) {
    asm volatile(
        "mma.sync.aligned.m16n8k8.row.col.f32.tf32.tf32.f32 "
        "{%0,%1,%2,%3}, {%4,%5,%6,%7}, {%8,%9}, {%0,%1,%2,%3};"
        : "+f"(d[0]), "+f"(d[1]), "+f"(d[2]), "+f"(d[3])
        : "r"(a[0]), "r"(a[1]), "r"(a[2]), "r"(a[3]), "r"(b[0]), "r"(b[1]));
}

// 1) LayerNorm (eps = 384)
__global__ void ln_kernel(const float* __restrict__ x, const float* __restrict__ g,
                          const float* __restrict__ b, float* __restrict__ out) {
    int w = threadIdx.x >> 5, lane = threadIdx.x & 31;
    int row = blockIdx.x * 4 + w;
    const float* xr = x + (size_t)row * Dn;
    float vals[12];
    #pragma unroll
    for (int p = 0; p < 3; p++) {
        float4 t = *reinterpret_cast<const float4*>(xr + (lane + 32 * p) * 4);
        vals[p*4+0]=t.x; vals[p*4+1]=t.y; vals[p*4+2]=t.z; vals[p*4+3]=t.w;
    }
    float s = 0.f;
    #pragma unroll
    for (int i = 0; i < 12; i++) s += vals[i];
    float mu = warp_sum(s) * (1.0f / Dn);
    float ss = 0.f;
    #pragma unroll
    for (int i = 0; i < 12; i++) { vals[i] -= mu; ss += vals[i]*vals[i]; }
    float rs = rsqrtf(warp_sum(ss) * (1.0f / Dn) + 384.0f);
    float* orow = out + (size_t)row * Dn;
    #pragma unroll
    for (int p = 0; p < 3; p++) {
        int c = (lane + 32 * p) * 4;
        float4 t;
        t.x = vals[p*4+0]*rs*g[c+0]+b[c+0]; t.y = vals[p*4+1]*rs*g[c+1]+b[c+1];
        t.z = vals[p*4+2]*rs*g[c+2]+b[c+2]; t.w = vals[p*4+3]*rs*g[c+3]+b[c+3];
        *reinterpret_cast<float4*>(orow + c) = t;
    }
}

// 2) tf32 GEMM (BM=128 BN=64 BK=32, 8 warps)
__global__ void gemm_tf32(const float* __restrict__ A, const float* __restrict__ W,
                          const float* __restrict__ bias, float* __restrict__ Cout,
                          const float* __restrict__ addend, float scale,
                          const int* __restrict__ flipPtr) {
    constexpr int K = 384, N = 384;
    __shared__ float As[128][36];
    __shared__ float Bs[64][36];
    int tid = threadIdx.x;
    int lane = tid & 31, wid = tid >> 5;
    int warp_m = wid & 3, warp_n = wid >> 2;
    int m0 = blockIdx.x * 128, n0 = blockIdx.y * 64;
    int gq = lane >> 2, tg = lane & 3;
    float acc[2][4][4];
    #pragma unroll
    for (int a = 0; a < 2; a++)
        #pragma unroll
        for (int b = 0; b < 4; b++)
            #pragma unroll
            for (int c = 0; c < 4; c++) acc[a][b][c] = 0.f;
    int ldrow = tid >> 3;
    int ldcol = (tid & 7) * 4;
    for (int k0 = 0; k0 < K; k0 += 32) {
        #pragma unroll
        for (int i = 0; i < 4; i++) {
            int m = ldrow + 32 * i;
            float4 v = *reinterpret_cast<const float4*>(A + (size_t)(m0+m)*K + k0 + ldcol);
            As[m][ldcol+0] = cvt_tf32(v.x); As[m][ldcol+1] = cvt_tf32(v.y);
            As[m][ldcol+2] = cvt_tf32(v.z); As[m][ldcol+3] = cvt_tf32(v.w);
        }
        #pragma unroll
        for (int i = 0; i < 2; i++) {
            int n = ldrow + 32 * i;
            float4 v = *reinterpret_cast<const float4*>(W + (size_t)(n0+n)*K + k0 + ldcol);
            Bs[n][ldcol+0] = cvt_tf32(v.x); Bs[n][ldcol+1] = cvt_tf32(v.y);
            Bs[n][ldcol+2] = cvt_tf32(v.z); Bs[n][ldcol+3] = cvt_tf32(v.w);
        }
        __syncthreads();
        #pragma unroll
        for (int kk = 0; kk < 32; kk += 8) {
            uint32_t af[2][4], bfr[4][2];
            #pragma unroll
            for (int mt = 0; mt < 2; mt++) {
                int mr = warp_m * 32 + mt * 16 + gq;
                af[mt][0] = __float_as_uint(As[mr    ][kk + tg]);
                af[mt][1] = __float_as_uint(As[mr + 8][kk + tg]);
                af[mt][2] = __float_as_uint(As[mr    ][kk + 4 + tg]);
                af[mt][3] = __float_as_uint(As[mr + 8][kk + 4 + tg]);
            }
            #pragma unroll
            for (int nt = 0; nt < 4; nt++) {
                int nr = warp_n * 32 + nt * 8 + gq;
                bfr[nt][0] = __float_as_uint(Bs[nr][kk + tg]);
                bfr[nt][1] = __float_as_uint(Bs[nr][kk + 4 + tg]);
            }
            #pragma unroll
            for (int mt = 0; mt < 2; mt++)
                #pragma unroll
                for (int nt = 0; nt < 4; nt++) mma_tf32(acc[mt][nt], af[mt], bfr[nt]);
        }
        __syncthreads();
    }
    int fl = flipPtr ? *flipPtr : 0;
    #pragma unroll
    for (int mt = 0; mt < 2; mt++) {
        int r0 = m0 + warp_m * 32 + mt * 16 + gq;
        int r1 = r0 + 8;
        #pragma unroll
        for (int nt = 0; nt < 4; nt++) {
            int col = n0 + warp_n * 32 + nt * 8 + tg * 2;
            float b0v = bias[col], b1v = bias[col + 1];
            float v00 = (acc[mt][nt][0] + b0v) * scale;
            float v01 = (acc[mt][nt][1] + b1v) * scale;
            float v10 = (acc[mt][nt][2] + b0v) * scale;
            float v11 = (acc[mt][nt][3] + b1v) * scale;
            if (addend) {
                v00 += addend[(size_t)r0 * N + col];
                v01 += addend[(size_t)r0 * N + col + 1];
                v10 += addend[(size_t)r1 * N + col];
                v11 += addend[(size_t)r1 * N + col + 1];
            }
            int ms0 = r0, ms1 = r1;
            if (fl) {
                ms0 = (r0 & ~2047) + (Sn - 1 - (r0 & 2047));
                ms1 = (r1 & ~2047) + (Sn - 1 - (r1 & 2047));
            }
            *reinterpret_cast<float2*>(Cout + (size_t)ms0 * N + col) = make_float2(v00, v01);
            *reinterpret_cast<float2*>(Cout + (size_t)ms1 * N + col) = make_float2(v10, v11);
        }
    }
}

// 3) causal depthwise conv (K=4) + SiLU
__global__ void conv_kernel(const float* __restrict__ left, const float* __restrict__ cw,
                            const float* __restrict__ cb, float* __restrict__ xc) {
    int bt = blockIdx.x;
    int b = bt >> 11, t = bt & 2047;
    #pragma unroll
    for (int p = 0; p < 3; p++) {
        int d = threadIdx.x + 128 * p;
        float acc = cb[d];
        #pragma unroll
        for (int j = 0; j < 4; j++) {
            int tt = t - 3 + j;
            if (tt >= 0) acc += cw[d*4+j] * left[((size_t)b*Sn + tt)*Dn + d];
        }
        xc[(size_t)bt*Dn + d] = acc / (1.0f + expf(-acc));
    }
}

// 4) ig / fg
__global__ void igfg_kernel(const float* __restrict__ left,
                            const float* __restrict__ Wi, const float* __restrict__ bi,
                            const float* __restrict__ Wf, const float* __restrict__ bf,
                            float* __restrict__ ig, float* __restrict__ fg) {
    __shared__ float Ar[16][385];
    __shared__ float Ws[12][385];
    int tid = threadIdx.x;
    int row0 = blockIdx.x * 16;
    for (int i = tid; i < 16 * Dn; i += 192) {
        int r = i / Dn, kk = i - r * Dn;
        Ar[r][kk] = left[((size_t)row0 + r) * Dn + kk];
    }
    for (int i = tid; i < 12 * Dn; i += 192) {
        int o = i / Dn, kk = i - o * Dn;
        Ws[o][kk] = (o < 6) ? Wi[o*Dn+kk] : Wf[(o-6)*Dn+kk];
    }
    __syncthreads();
    int r = tid / 12, o = tid - r * 12;
    float acc = 0.f;
    #pragma unroll 4
    for (int kk = 0; kk < Dn; kk++) acc += Ar[r][kk] * Ws[o][kk];
    int row = row0 + r;
    if (o < 6) ig[(size_t)row*Hn + o] = acc + bi[o];
    else {
        int h = o - 6;
        float z = acc + bf[h];
        fg[(size_t)row*Hn + h] = fminf(z, 0.f) - log1pf(expf(-fabsf(z)));
    }
}

// 5) gates: closed-form m (stored); fe/ie; n-scan + 1/den (k,q staged in smem)
__global__ void gates_kernel(const float* __restrict__ ig, const float* __restrict__ fg,
                             const float* __restrict__ k, const float* __restrict__ q,
                             float* __restrict__ fe, float* __restrict__ ie,
                             float* __restrict__ mOut, float* __restrict__ rd) {
    __shared__ float sh[64*68*2 + 128];
    float* kbuf = sh;
    float* qbuf = sh + 64*68;
    float* fes  = sh + 64*68*2;
    float* ies  = fes + 64;
    float* sF = sh; float* sG = sh + 256; float* oFp = sh + 512; float* pGp = sh + 768;

    int bh = blockIdx.x;
    int b = bh / Hn, h = bh - b * Hn;
    int tid = threadIdx.x; // 256
    const size_t gbase = (size_t)bh * Sn;

    float fgl[8], igl[8], Fl[8], Gl[8];
    int tbase = tid * 8;
    #pragma unroll
    for (int j = 0; j < 8; j++) {
        int t = tbase + j;
        fgl[j] = fg[((size_t)b*Sn + t)*Hn + h];
        igl[j] = ig[((size_t)b*Sn + t)*Hn + h];
    }
    float F = 0.f, G = -INFINITY;
    #pragma unroll
    for (int j = 0; j < 8; j++) {
        F += fgl[j]; Fl[j] = F;
        G = fmaxf(G, igl[j] - F); Gl[j] = G;
    }
    sF[tid] = F; sG[tid] = G;
    __syncthreads();
    if (tid == 0) {
        float aF = 0.f, aG = -INFINITY;
        for (int i = 0; i < 256; i++) {
            oFp[i] = aF; pGp[i] = aG;
            aG = fmaxf(aG, sG[i] - aF);
            aF += sF[i];
        }
    }
    __syncthreads();
    float oF = oFp[tid], pG = pGp[tid];
    float mp = oF + pG;
    #pragma unroll
    for (int j = 0; j < 8; j++) {
        float Ft = oF + Fl[j];
        float Gt = fmaxf(pG, Gl[j] - oF);
        float m = Ft + Gt;
        fe[gbase + tbase + j] = expf(fgl[j] + mp - m);
        ie[gbase + tbase + j] = expf(igl[j] - m);
        mOut[gbase + tbase + j] = m;
        mp = m;
    }
    __syncthreads();

    float nreg = 0.f;
    for (int t0 = 0; t0 < Sn; t0 += 64) {
        #pragma unroll
        for (int p = 0; p < 4; p++) {
            int idx = tid + 256 * p;            // 1024 float4 slots
            int tt = idx >> 4, j4 = (idx & 15) << 2;
            size_t go = ((size_t)b*Sn + t0 + tt)*Dn + h*DHn + j4;
            *reinterpret_cast<float4*>(&kbuf[tt*68 + j4]) = *reinterpret_cast<const float4*>(k + go);
            *reinterpret_cast<float4*>(&qbuf[tt*68 + j4]) = *reinterpret_cast<const float4*>(q + go);
        }
        if (tid < 64) fes[tid] = fe[gbase + t0 + tid];
        else if (tid < 128) ies[tid-64] = ie[gbase + t0 + tid - 64];
        __syncthreads();
        if (tid < 64) {
            #pragma unroll 4
            for (int tt = 0; tt < 64; tt++) {
                nreg = fes[tt] * nreg + ies[tt] * kbuf[tt*68 + tid];
                kbuf[tt*68 + tid] = nreg;
            }
        }
        __syncthreads();
        if (tid < 64) {
            float den = 0.f;
            #pragma unroll 8
            for (int j = 0; j < 64; j++) den += kbuf[tid*68 + j] * qbuf[tid*68 + j];
            rd[gbase + t0 + tid] = 1.0f / fmaxf(fabsf(den), 1.0f);
        }
        __syncthreads();
    }
}

// 6a) chunk phase A: log-space anchored scaling; S=tril(Q'K'^T), intra=S@V, G=V^T K'.
__global__ void chunkA(float* __restrict__ q, const float* __restrict__ k,
                       const float* __restrict__ v,
                       const float* __restrict__ ig, const float* __restrict__ fg,
                       const float* __restrict__ mArr,
                       float* __restrict__ hintra, float* __restrict__ Gout,
                       float* __restrict__ SC) {
    extern __shared__ float sm[];
    float* sQ = sm;              // 64*68 (later S)
    float* sK = sm + 64*68;
    float* sV = sm + 2*64*68;
    float* sfg = sm + 3*64*68;   // 64
    float* sig_ = sfg + 64;
    float* smv = sig_ + 64;
    float* sFl = smv + 64;
    float* sRow = sFl + 64;
    float* sCol = sRow + 64;
    float* sScal = sCol + 64;    // 4

    int c = blockIdx.x, bh = blockIdx.y;
    int b = bh / Hn, h = bh - b * Hn;
    int t0 = c * 64;
    int tid = threadIdx.x;       // 128
    int lane = tid & 31, w = tid >> 5;
    int gq = lane >> 2, tg = lane & 3;
    size_t gbase = (size_t)bh * Sn + t0;

    if (tid < 64) {
        int t = t0 + tid;
        sfg[tid]  = fg[((size_t)b*Sn + t)*Hn + h];
        sig_[tid] = ig[((size_t)b*Sn + t)*Hn + h];
        smv[tid]  = mArr[gbase + tid];
    }
    __syncthreads();
    if (tid == 0) {
        float Fl = 0.f, AA = -INFINITY;
        for (int i = 0; i < 64; i++) {
            Fl += sfg[i]; sFl[i] = Fl;
            AA = fmaxf(AA, sig_[i] - Fl);
        }
        float mT1 = smv[63];
        bool first = (c == 0);
        float Ac = first ? 0.f : mArr[gbase - 1];
        sScal[0] = first ? 0.f : expf(Ac - AA);              // s_c
        sScal[1] = first ? 0.f : expf(sFl[63] + Ac - mT1);   // PL
        sScal[2] = expf(AA + sFl[63] - mT1);                 // gfac
        sScal[3] = AA;
    }
    __syncthreads();
    if (tid < 64) {
        float AA = sScal[3];
        sRow[tid] = expf(sFl[tid] - smv[tid] + AA);
        sCol[tid] = expf(sig_[tid] - sFl[tid] - AA);
    }
    if (tid >= 64 && tid < 67) SC[(size_t)(bh*NC + c)*4 + (tid - 64)] = sScal[tid - 64];
    __syncthreads();

    {
        int i = tid >> 1, hf = tid & 1;
        size_t ro = ((size_t)b*Sn + t0 + i)*Dn + h*DHn + hf*32;
        float rsc = sRow[i];
        float csc = sCol[i];
        #pragma unroll
        for (int p = 0; p < 8; p++) {
            int j = hf*32 + p*4;
            float4 qv = *reinterpret_cast<const float4*>(q + ro + p*4);
            float4 kv = *reinterpret_cast<const float4*>(k + ro + p*4);
            float4 vv = *reinterpret_cast<const float4*>(v + ro + p*4);
            qv.x *= rsc; qv.y *= rsc; qv.z *= rsc; qv.w *= rsc;
            *reinterpret_cast<float4*>(q + ro + p*4) = qv;    // Q' in place
            sQ[i*68+j+0]=cvt_tf32(qv.x); sQ[i*68+j+1]=cvt_tf32(qv.y);
            sQ[i*68+j+2]=cvt_tf32(qv.z); sQ[i*68+j+3]=cvt_tf32(qv.w);
            sK[i*68+j+0]=cvt_tf32(kv.x*csc); sK[i*68+j+1]=cvt_tf32(kv.y*csc);
            sK[i*68+j+2]=cvt_tf32(kv.z*csc); sK[i*68+j+3]=cvt_tf32(kv.w*csc);
            sV[i*68+j+0]=cvt_tf32(vv.x); sV[i*68+j+1]=cvt_tf32(vv.y);
            sV[i*68+j+2]=cvt_tf32(vv.z); sV[i*68+j+3]=cvt_tf32(vv.w);
        }
    }
    __syncthreads();

    // GEMM1: S = Q' @ K'^T
    float accS[8][4];
    #pragma unroll
    for (int nt = 0; nt < 8; nt++)
        #pragma unroll
        for (int x = 0; x < 4; x++) accS[nt][x] = 0.f;
    int m0 = w * 16;
    #pragma unroll
    for (int kk = 0; kk < 64; kk += 8) {
        uint32_t af[4];
        af[0] = __float_as_uint(sQ[(m0+gq)*68 + kk+tg]);
        af[1] = __float_as_uint(sQ[(m0+gq+8)*68 + kk+tg]);
        af[2] = __float_as_uint(sQ[(m0+gq)*68 + kk+4+tg]);
        af[3] = __float_as_uint(sQ[(m0+gq+8)*68 + kk+4+tg]);
        #pragma unroll
        for (int nt = 0; nt < 8; nt++) {
            uint32_t bf[2];
            bf[0] = __float_as_uint(sK[(nt*8+gq)*68 + kk+tg]);
            bf[1] = __float_as_uint(sK[(nt*8+gq)*68 + kk+4+tg]);
            mma_tf32(accS[nt], af, bf);
        }
    }
    __syncthreads();
    #pragma unroll
    for (int nt = 0; nt < 8; nt++) {
        int r0 = m0 + gq, r1 = r0 + 8;
        int c0 = nt*8 + tg*2, c1 = c0 + 1;
        sQ[r0*68 + c0] = (c0 <= r0) ? cvt_tf32(accS[nt][0]) : 0.f;
        sQ[r0*68 + c1] = (c1 <= r0) ? cvt_tf32(accS[nt][1]) : 0.f;
        sQ[r1*68 + c0] = (c0 <= r1) ? cvt_tf32(accS[nt][2]) : 0.f;
        sQ[r1*68 + c1] = (c1 <= r1) ? cvt_tf32(accS[nt][3]) : 0.f;
    }
    __syncthreads();

    // GEMM2: intra = S @ V
    float accI[8][4];
    #pragma unroll
    for (int nt = 0; nt < 8; nt++)
        #pragma unroll
        for (int x = 0; x < 4; x++) accI[nt][x] = 0.f;
    #pragma unroll
    for (int kk = 0; kk < 64; kk += 8) {
        uint32_t af[4];
        af[0] = __float_as_uint(sQ[(m0+gq)*68 + kk+tg]);
        af[1] = __float_as_uint(sQ[(m0+gq+8)*68 + kk+tg]);
        af[2] = __float_as_uint(sQ[(m0+gq)*68 + kk+4+tg]);
        af[3] = __float_as_uint(sQ[(m0+gq+8)*68 + kk+4+tg]);
        #pragma unroll
        for (int nt = 0; nt < 8; nt++) {
            uint32_t bf[2];
            bf[0] = __float_as_uint(sV[(kk+tg)*68 + nt*8+gq]);
            bf[1] = __float_as_uint(sV[(kk+4+tg)*68 + nt*8+gq]);
            mma_tf32(accI[nt], af, bf);
        }
    }
    #pragma unroll
    for (int nt = 0; nt < 8; nt++) {
        int r0 = m0 + gq, r1 = r0 + 8;
        int c0 = nt*8 + tg*2;
        size_t o0 = (gbase + r0) * DHn + c0;
        size_t o1 = (gbase + r1) * DHn + c0;
        *reinterpret_cast<float2*>(hintra + o0) = make_float2(accI[nt][0], accI[nt][1]);
        *reinterpret_cast<float2*>(hintra + o1) = make_float2(accI[nt][2], accI[nt][3]);
    }

    // GEMM3: G = V^T @ K'
    float accG[8][4];
    #pragma unroll
    for (int nt = 0; nt < 8; nt++)
        #pragma unroll
        for (int x = 0; x < 4; x++) accG[nt][x] = 0.f;
    #pragma unroll
    for (int kk = 0; kk < 64; kk += 8) {
        uint32_t af[4];
        af[0] = __float_as_uint(sV[(kk+tg)*68 + m0+gq]);
        af[1] = __float_as_uint(sV[(kk+tg)*68 + m0+gq+8]);
        af[2] = __float_as_uint(sV[(kk+4+tg)*68 + m0+gq]);
        af[3] = __float_as_uint(sV[(kk+4+tg)*68 + m0+gq+8]);
        #pragma unroll
        for (int nt = 0; nt < 8; nt++) {
            uint32_t bf[2];
            bf[0] = __float_as_uint(sK[(kk+tg)*68 + nt*8+gq]);
            bf[1] = __float_as_uint(sK[(kk+4+tg)*68 + nt*8+gq]);
            mma_tf32(accG[nt], af, bf);
        }
    }
    size_t Gb = ((size_t)bh*NC + c) * DHn * DHn;
    #pragma unroll
    for (int nt = 0; nt < 8; nt++) {
        int r0 = m0 + gq, r1 = r0 + 8;
        int c0 = nt*8 + tg*2;
        *reinterpret_cast<float2*>(Gout + Gb + (size_t)r0*DHn + c0) = make_float2(accG[nt][0], accG[nt][1]);
        *reinterpret_cast<float2*>(Gout + Gb + (size_t)r1*DHn + c0) = make_float2(accG[nt][2], accG[nt][3]);
    }
}

// 6b) phase B: serial over chunks. Ninter = s_c*(Q' @ C^T); h=(intra+Ninter)*rd;
//     C = PL*C + gfac*G.
__global__ void chunkB(const float* __restrict__ qp, const float* __restrict__ Gin,
                       const float* __restrict__ SC, const float* __restrict__ rd,
                       float* __restrict__ hio) {
    __shared__ float sC[64*68];
    __shared__ float sQ[64*68];
    int bh = blockIdx.x;
    int b = bh / Hn, h = bh - b * Hn;
    int tid = threadIdx.x;  // 128
    int lane = tid & 31, w = tid >> 5;
    int gq = lane >> 2, tg = lane & 3;
    int m0 = w * 16;
    int r = tid >> 1, hf = tid & 1;

    float Creg[32];
    #pragma unroll
    for (int j = 0; j < 32; j++) Creg[j] = 0.f;
    for (int idx = tid; idx < 64*68; idx += 128) sC[idx] = 0.f;
    __syncthreads();

    for (int c = 0; c < NC; c++) {
        int t0 = c * 64;
        float s_c  = SC[(size_t)(bh*NC + c)*4 + 0];
        float PLc  = SC[(size_t)(bh*NC + c)*4 + 1];
        float gfac = SC[(size_t)(bh*NC + c)*4 + 2];
        {
            size_t ro = ((size_t)b*Sn + t0 + r)*Dn + h*DHn + hf*32;
            #pragma unroll
            for (int p = 0; p < 8; p++) {
                float4 qv = *reinterpret_cast<const float4*>(qp + ro + p*4);
                int j = hf*32 + p*4;
                sQ[r*68+j+0]=cvt_tf32(qv.x); sQ[r*68+j+1]=cvt_tf32(qv.y);
                sQ[r*68+j+2]=cvt_tf32(qv.z); sQ[r*68+j+3]=cvt_tf32(qv.w);
            }
        }
        __syncthreads();
        float acc[8][4];
        #pragma unroll
        for (int nt = 0; nt < 8; nt++)
            #pragma unroll
            for (int x = 0; x < 4; x++) acc[nt][x] = 0.f;
        #pragma unroll
        for (int kk = 0; kk < 64; kk += 8) {
            uint32_t af[4];
            af[0] = __float_as_uint(sQ[(m0+gq)*68 + kk+tg]);
            af[1] = __float_as_uint(sQ[(m0+gq+8)*68 + kk+tg]);
            af[2] = __float_as_uint(sQ[(m0+gq)*68 + kk+4+tg]);
            af[3] = __float_as_uint(sQ[(m0+gq+8)*68 + kk+4+tg]);
            #pragma unroll
            for (int nt = 0; nt < 8; nt++) {
                uint32_t bf[2];
                bf[0] = __float_as_uint(sC[(nt*8+gq)*68 + kk+tg]);
                bf[1] = __float_as_uint(sC[(nt*8+gq)*68 + kk+4+tg]);
                mma_tf32(acc[nt], af, bf);
            }
        }
        #pragma unroll
        for (int nt = 0; nt < 8; nt++) {
            int r0 = m0 + gq, r1 = r0 + 8;
            int c0 = nt*8 + tg*2;
            size_t u0 = (size_t)bh*Sn + t0 + r0;
            size_t u1 = (size_t)bh*Sn + t0 + r1;
            float rd0 = rd[u0], rd1 = rd[u1];
            float2 i0 = *reinterpret_cast<const float2*>(hio + u0*DHn + c0);
            float2 i1 = *reinterpret_cast<const float2*>(hio + u1*DHn + c0);
            *reinterpret_cast<float2*>(hio + u0*DHn + c0) =
                make_float2((i0.x + s_c*acc[nt][0]) * rd0, (i0.y + s_c*acc[nt][1]) * rd0);
            *reinterpret_cast<float2*>(hio + u1*DHn + c0) =
                make_float2((i1.x + s_c*acc[nt][2]) * rd1, (i1.y + s_c*acc[nt][3]) * rd1);
        }
        __syncthreads();
        size_t Gb = ((size_t)bh*NC + c) * DHn * DHn + (size_t)r*DHn + hf*32;
        #pragma unroll
        for (int p = 0; p < 8; p++) {
            float4 gv = *reinterpret_cast<const float4*>(Gin + Gb + p*4);
            int j = p*4;
            Creg[j+0] = PLc * Creg[j+0] + gfac * gv.x;
            Creg[j+1] = PLc * Creg[j+1] + gfac * gv.y;
            Creg[j+2] = PLc * Creg[j+2] + gfac * gv.z;
            Creg[j+3] = PLc * Creg[j+3] + gfac * gv.w;
            int cc = hf*32 + j;
            sC[r*68+cc+0]=cvt_tf32(Creg[j+0]); sC[r*68+cc+1]=cvt_tf32(Creg[j+1]);
            sC[r*68+cc+2]=cvt_tf32(Creg[j+2]); sC[r*68+cc+3]=cvt_tf32(Creg[j+3]);
        }
        __syncthreads();
    }
}

// 7) GroupNorm + unflip + multiply by LN out
__global__ void gnprod_kernel(const float* __restrict__ hin,
                              const float* __restrict__ gn_g, const float* __restrict__ gn_b,
                              const float* __restrict__ outln,
                              const int* __restrict__ flipPtr,
                              float* __restrict__ prod) {
    int w = threadIdx.x >> 5, lane = threadIdx.x & 31;
    int u = blockIdx.x * 8 + w;
    int b = u / (Hn * Sn);
    int rem = u - b * (Hn * Sn);
    int h = rem / Sn, t = rem - h * Sn;
    float v0 = hin[(size_t)u*DHn + lane];
    float v1 = hin[(size_t)u*DHn + 32 + lane];
    float mu = warp_sum(v0 + v1) * (1.0f / DHn);
    float x0 = v0 - mu, x1 = v1 - mu;
    float rs = rsqrtf(warp_sum(x0*x0 + x1*x1) * (1.0f / DHn) + 1e-5f);
    int d0 = h*DHn + lane, d1 = d0 + 32;
    float hn0 = x0*rs*gn_g[d0] + gn_b[d0];
    float hn1 = x1*rs*gn_g[d1] + gn_b[d1];
    int s = (*flipPtr) ? (Sn - 1 - t) : t;
    size_t row = ((size_t)b*Sn + s) * Dn;
    prod[row + d0] = hn0 * outln[row + d0];
    prod[row + d1] = hn1 * outln[row + d1];
}

extern "C" void kernel_launch(void* const* d_in, const int* in_sizes, int n_in,
                              void* d_out, int out_size) {
    const float* x    = (const float*)d_in[0];
    const float* ln_g = (const float*)d_in[1];
    const float* ln_b = (const float*)d_in[2];
    const float* W2   = (const float*)d_in[5];
    const float* b2   = (const float*)d_in[6];
    const float* W3   = (const float*)d_in[7];
    const float* b3   = (const float*)d_in[8];
    const float* cw   = (const float*)d_in[9];
    const float* cb   = (const float*)d_in[10];
    const float* Wq   = (const float*)d_in[11];
    const float* bq   = (const float*)d_in[12];
    const float* Wk   = (const float*)d_in[13];
    const float* bk   = (const float*)d_in[14];
    const float* Wv   = (const float*)d_in[15];
    const float* bv   = (const float*)d_in[16];
    const float* Wi   = (const float*)d_in[17];
    const float* bi   = (const float*)d_in[18];
    const float* Wf   = (const float*)d_in[19];
    const float* bf   = (const float*)d_in[20];
    const float* gn_g = (const float*)d_in[21];
    const float* gn_b = (const float*)d_in[22];
    const int*   flip = (const int*)d_in[23];
    float* out = (float*)d_out;

    float *p_out, *p_left, *p_xc, *p_q, *p_k, *p_v, *p_ig, *p_fg,
          *p_fe, *p_ie, *p_m, *p_rd, *p_h, *p_G, *p_SC, *p_prod;
    cudaGetSymbolAddress((void**)&p_out,  g_out);
    cudaGetSymbolAddress((void**)&p_left, g_left);
    cudaGetSymbolAddress((void**)&p_xc,   g_xc);
    cudaGetSymbolAddress((void**)&p_q,    g_q);
    cudaGetSymbolAddress((void**)&p_k,    g_k);
    cudaGetSymbolAddress((void**)&p_v,    g_v);
    cudaGetSymbolAddress((void**)&p_ig,   g_ig);
    cudaGetSymbolAddress((void**)&p_fg,   g_fg);
    cudaGetSymbolAddress((void**)&p_fe,   g_fe);
    cudaGetSymbolAddress((void**)&p_ie,   g_ie);
    cudaGetSymbolAddress((void**)&p_m,    g_m);
    cudaGetSymbolAddress((void**)&p_rd,   g_rd);
    cudaGetSymbolAddress((void**)&p_h,    g_h);
    cudaGetSymbolAddress((void**)&p_G,    g_G);
    cudaGetSymbolAddress((void**)&p_SC,   g_SC);
    cudaGetSymbolAddress((void**)&p_prod, g_prod);

    cudaError_t attr_ok = cudaFuncSetAttribute(
        chunkA, cudaFuncAttributeMaxDynamicSharedMemorySize, 54560);
    (void)attr_ok;

    dim3 ggrid(BSn / 128, Dn / 64);

    ln_kernel<<<BSn / 4, 128>>>(x, ln_g, ln_b, p_out);
    gemm_tf32<<<ggrid, 256>>>(p_out, W2, b2, p_left, nullptr, 1.0f, flip);
    conv_kernel<<<BSn, 128>>>(p_left, cw, cb, p_xc);
    gemm_tf32<<<ggrid, 256>>>(p_xc,   Wq, bq, p_q, nullptr, 1.0f,   nullptr);
    gemm_tf32<<<ggrid, 256>>>(p_xc,   Wk, bk, p_k, nullptr, 0.125f, nullptr);
    gemm_tf32<<<ggrid, 256>>>(p_left, Wv, bv, p_v, nullptr, 1.0f,   nullptr);
    igfg_kernel<<<BSn / 16, 192>>>(p_left, Wi, bi, Wf, bf, p_ig, p_fg);
    gates_kernel<<<BHn, 256>>>(p_ig, p_fg, p_k, p_q, p_fe, p_ie, p_m, p_rd);
    chunkA<<<dim3(NC, BHn), 128, 54560>>>(p_q, p_k, p_v, p_ig, p_fg, p_m, p_h, p_G, p_SC);
    chunkB<<<BHn, 128>>>(p_q, p_G, p_SC, p_rd, p_h);
    gnprod_kernel<<<(BHn * Sn) / 8, 256>>>(p_h, gn_g, gn_b, p_out, flip, p_prod);
    gemm_tf32<<<ggrid, 256>>>(p_prod, W3, b3, out, x, 1.0f, nullptr);
}

// round 8
// speedup vs baseline: 2.7533x; 1.0823x over previous
#include <cuda_runtime.h>
#include <cstdint>
#include <cstddef>
#include <math.h>

static constexpr int Bn = 8;
static constexpr int Sn = 2048;
static constexpr int Dn = 384;
static constexpr int Hn = 6;
static constexpr int DHn = 64;
static constexpr int BSn = Bn * Sn;   // 16384
static constexpr int BHn = Bn * Hn;   // 48
static constexpr int NC = Sn / 64;    // 32 chunks

__device__ float g_out [BSn * Dn];
__device__ float g_left[BSn * Dn];
__device__ float g_xc  [BSn * Dn];
__device__ float g_q   [BSn * Dn];
__device__ float g_k   [BSn * Dn];
__device__ float g_v   [BSn * Dn];
__device__ float g_ig  [BSn * Hn];
__device__ float g_fg  [BSn * Hn];
__device__ float g_fe  [BHn * Sn];
__device__ float g_ie  [BHn * Sn];
__device__ float g_m   [BHn * Sn];
__device__ float g_rd  [BHn * Sn];
__device__ float g_h   [(size_t)BHn * Sn * DHn];
__device__ float g_G   [(size_t)BHn * NC * DHn * DHn];
__device__ float g_SC  [BHn * NC * 4];
__device__ float g_prod[BSn * Dn];

__device__ __forceinline__ float warp_sum(float v) {
    #pragma unroll
    for (int o = 16; o > 0; o >>= 1) v += __shfl_xor_sync(0xffffffffu, v, o);
    return v;
}
__device__ __forceinline__ float cvt_tf32(float x) {
    uint32_t o;
    asm("cvt.rna.tf32.f32 %0, %1;" : "=r"(o) : "f"(x));
    return __uint_as_float(o);
}
__device__ __forceinline__ void mma_tf32(float* d, const uint32_t* a, const uint32_t* b) {
    asm volatile(
        "mma.sync.aligned.m16n8k8.row.col.f32.tf32.tf32.f32 "
        "{%0,%1,%2,%3}, {%4,%5,%6,%7}, {%8,%9}, {%0,%1,%2,%3};"
        : "+f"(d[0]), "+f"(d[1]), "+f"(d[2]), "+f"(d[3])
        : "r"(a[0]), "r"(a[1]), "r"(a[2]), "r"(a[3]), "r"(b[0]), "r"(b[1]));
}
__device__ __forceinline__ void cp_async16(void* smem_dst, const void* gsrc) {
    uint32_t dst = (uint32_t)__cvta_generic_to_shared(smem_dst);
    asm volatile("cp.async.ca.shared.global [%0], [%1], 16;" :: "r"(dst), "l"(gsrc));
}

// 1) LayerNorm (eps = 384)
__global__ void ln_kernel(const float* __restrict__ x, const float* __restrict__ g,
                          const float* __restrict__ b, float* __restrict__ out) {
    int w = threadIdx.x >> 5, lane = threadIdx.x & 31;
    int row = blockIdx.x * 4 + w;
    const float* xr = x + (size_t)row * Dn;
    float vals[12];
    #pragma unroll
    for (int p = 0; p < 3; p++) {
        float4 t = *reinterpret_cast<const float4*>(xr + (lane + 32 * p) * 4);
        vals[p*4+0]=t.x; vals[p*4+1]=t.y; vals[p*4+2]=t.z; vals[p*4+3]=t.w;
    }
    float s = 0.f;
    #pragma unroll
    for (int i = 0; i < 12; i++) s += vals[i];
    float mu = warp_sum(s) * (1.0f / Dn);
    float ss = 0.f;
    #pragma unroll
    for (int i = 0; i < 12; i++) { vals[i] -= mu; ss += vals[i]*vals[i]; }
    float rs = rsqrtf(warp_sum(ss) * (1.0f / Dn) + 384.0f);
    float* orow = out + (size_t)row * Dn;
    #pragma unroll
    for (int p = 0; p < 3; p++) {
        int c = (lane + 32 * p) * 4;
        float4 t;
        t.x = vals[p*4+0]*rs*g[c+0]+b[c+0]; t.y = vals[p*4+1]*rs*g[c+1]+b[c+1];
        t.z = vals[p*4+2]*rs*g[c+2]+b[c+2]; t.w = vals[p*4+3]*rs*g[c+3]+b[c+3];
        *reinterpret_cast<float4*>(orow + c) = t;
    }
}

// 2) tf32 GEMM, cp.async double-buffered. BM=128 BN=64 BK=16, 8 warps.
__global__ void gemm_tf32(const float* __restrict__ A, const float* __restrict__ W,
                          const float* __restrict__ bias, float* __restrict__ Cout,
                          const float* __restrict__ addend, float scale,
                          const int* __restrict__ flipPtr) {
    constexpr int K = 384, N = 384;
    constexpr int LDA = 20;
    __shared__ float As[2][128 * LDA];
    __shared__ float Bs[2][64 * LDA];
    int tid = threadIdx.x;
    int lane = tid & 31, wid = tid >> 5;
    int warp_m = wid & 3, warp_n = wid >> 2;
    int m0 = blockIdx.x * 128, n0 = blockIdx.y * 64;
    int gq = lane >> 2, tg = lane & 3;
    float acc[2][4][4];
    #pragma unroll
    for (int a = 0; a < 2; a++)
        #pragma unroll
        for (int b = 0; b < 4; b++)
            #pragma unroll
            for (int c = 0; c < 4; c++) acc[a][b][c] = 0.f;

    auto issue = [&](int buf, int k0) {
        #pragma unroll
        for (int p = 0; p < 2; p++) {
            int idx = tid + 256 * p;
            int m = idx >> 2, c4 = (idx & 3) << 2;
            cp_async16(&As[buf][m * LDA + c4], A + (size_t)(m0 + m) * K + k0 + c4);
        }
        {
            int n = tid >> 2, c4 = (tid & 3) << 2;
            cp_async16(&Bs[buf][n * LDA + c4], W + (size_t)(n0 + n) * K + k0 + c4);
        }
        asm volatile("cp.async.commit_group;");
    };

    issue(0, 0);
    constexpr int NIT = K / 16;  // 24
    for (int it = 0; it < NIT; it++) {
        if (it + 1 < NIT) {
            issue((it + 1) & 1, (it + 1) * 16);
            asm volatile("cp.async.wait_group 1;");
        } else {
            asm volatile("cp.async.wait_group 0;");
        }
        __syncthreads();
        const float* Ab = As[it & 1];
        const float* Bb = Bs[it & 1];
        #pragma unroll
        for (int kk = 0; kk < 16; kk += 8) {
            uint32_t af[2][4], bfr[4][2];
            #pragma unroll
            for (int mt = 0; mt < 2; mt++) {
                int mr = warp_m * 32 + mt * 16 + gq;
                af[mt][0] = __float_as_uint(Ab[ mr      * LDA + kk + tg]);
                af[mt][1] = __float_as_uint(Ab[(mr + 8) * LDA + kk + tg]);
                af[mt][2] = __float_as_uint(Ab[ mr      * LDA + kk + 4 + tg]);
                af[mt][3] = __float_as_uint(Ab[(mr + 8) * LDA + kk + 4 + tg]);
            }
            #pragma unroll
            for (int nt = 0; nt < 4; nt++) {
                int nr = warp_n * 32 + nt * 8 + gq;
                bfr[nt][0] = __float_as_uint(Bb[nr * LDA + kk + tg]);
                bfr[nt][1] = __float_as_uint(Bb[nr * LDA + kk + 4 + tg]);
            }
            #pragma unroll
            for (int mt = 0; mt < 2; mt++)
                #pragma unroll
                for (int nt = 0; nt < 4; nt++) mma_tf32(acc[mt][nt], af[mt], bfr[nt]);
        }
        __syncthreads();
    }

    int fl = flipPtr ? *flipPtr : 0;
    #pragma unroll
    for (int mt = 0; mt < 2; mt++) {
        int r0 = m0 + warp_m * 32 + mt * 16 + gq;
        int r1 = r0 + 8;
        #pragma unroll
        for (int nt = 0; nt < 4; nt++) {
            int col = n0 + warp_n * 32 + nt * 8 + tg * 2;
            float b0v = bias[col], b1v = bias[col + 1];
            float v00 = (acc[mt][nt][0] + b0v) * scale;
            float v01 = (acc[mt][nt][1] + b1v) * scale;
            float v10 = (acc[mt][nt][2] + b0v) * scale;
            float v11 = (acc[mt][nt][3] + b1v) * scale;
            if (addend) {
                v00 += addend[(size_t)r0 * N + col];
                v01 += addend[(size_t)r0 * N + col + 1];
                v10 += addend[(size_t)r1 * N + col];
                v11 += addend[(size_t)r1 * N + col + 1];
            }
            int ms0 = r0, ms1 = r1;
            if (fl) {
                ms0 = (r0 & ~2047) + (Sn - 1 - (r0 & 2047));
                ms1 = (r1 & ~2047) + (Sn - 1 - (r1 & 2047));
            }
            *reinterpret_cast<float2*>(Cout + (size_t)ms0 * N + col) = make_float2(v00, v01);
            *reinterpret_cast<float2*>(Cout + (size_t)ms1 * N + col) = make_float2(v10, v11);
        }
    }
}

// 3) causal depthwise conv (K=4) + SiLU
__global__ void conv_kernel(const float* __restrict__ left, const float* __restrict__ cw,
                            const float* __restrict__ cb, float* __restrict__ xc) {
    int bt = blockIdx.x;
    int b = bt >> 11, t = bt & 2047;
    #pragma unroll
    for (int p = 0; p < 3; p++) {
        int d = threadIdx.x + 128 * p;
        float acc = cb[d];
        #pragma unroll
        for (int j = 0; j < 4; j++) {
            int tt = t - 3 + j;
            if (tt >= 0) acc += cw[d*4+j] * left[((size_t)b*Sn + tt)*Dn + d];
        }
        xc[(size_t)bt*Dn + d] = acc / (1.0f + expf(-acc));
    }
}

// 4) ig / fg: warp-per-row, register dot products + warp reductions
__global__ void igfg_kernel(const float* __restrict__ left,
                            const float* __restrict__ Wi, const float* __restrict__ bi,
                            const float* __restrict__ Wf, const float* __restrict__ bf,
                            float* __restrict__ ig, float* __restrict__ fg) {
    __shared__ float sW[12 * 384];
    __shared__ float sA[8 * 384];
    int tid = threadIdx.x;      // 256
    int w = tid >> 5, lane = tid & 31;
    int row0 = blockIdx.x * 8;
    // stage weights (Wi rows 0-5, Wf rows 6-11)
    for (int i = tid; i < 1152; i += 256) {
        int o = i / 96, j = (i - o * 96) * 4;
        const float* src = (o < 6) ? (Wi + o * 384 + j) : (Wf + (o - 6) * 384 + j);
        *reinterpret_cast<float4*>(&sW[o * 384 + j]) = *reinterpret_cast<const float4*>(src);
    }
    // stage 8 rows
    for (int i = tid; i < 768; i += 256) {
        int r = i / 96, j = (i - r * 96) * 4;
        *reinterpret_cast<float4*>(&sA[r * 384 + j]) =
            *reinterpret_cast<const float4*>(left + ((size_t)row0 + r) * 384 + j);
    }
    __syncthreads();
    float a[12];
    #pragma unroll
    for (int p = 0; p < 3; p++) {
        float4 t = *reinterpret_cast<const float4*>(&sA[w * 384 + lane * 12 + p * 4]);
        a[p*4+0]=t.x; a[p*4+1]=t.y; a[p*4+2]=t.z; a[p*4+3]=t.w;
    }
    float res[12];
    #pragma unroll
    for (int o = 0; o < 12; o++) {
        float s = 0.f;
        #pragma unroll
        for (int p = 0; p < 3; p++) {
            float4 t = *reinterpret_cast<const float4*>(&sW[o * 384 + lane * 12 + p * 4]);
            s += a[p*4+0]*t.x + a[p*4+1]*t.y + a[p*4+2]*t.z + a[p*4+3]*t.w;
        }
        res[o] = warp_sum(s);
    }
    if (lane == 0) {
        int row = row0 + w;
        #pragma unroll
        for (int o = 0; o < 6; o++) ig[(size_t)row * Hn + o] = res[o] + bi[o];
        #pragma unroll
        for (int o = 0; o < 6; o++) {
            float z = res[6 + o] + bf[o];
            fg[(size_t)row * Hn + o] = fminf(z, 0.f) - log1pf(expf(-fabsf(z)));
        }
    }
}

// 5) gates: closed-form m (stored); fe/ie; n-scan + 1/den (k,q staged in smem)
__global__ void gates_kernel(const float* __restrict__ ig, const float* __restrict__ fg,
                             const float* __restrict__ k, const float* __restrict__ q,
                             float* __restrict__ fe, float* __restrict__ ie,
                             float* __restrict__ mOut, float* __restrict__ rd) {
    __shared__ float sh[64*68*2 + 128];
    float* kbuf = sh;
    float* qbuf = sh + 64*68;
    float* fes  = sh + 64*68*2;
    float* ies  = fes + 64;
    float* sF = sh; float* sG = sh + 256; float* oFp = sh + 512; float* pGp = sh + 768;

    int bh = blockIdx.x;
    int b = bh / Hn, h = bh - b * Hn;
    int tid = threadIdx.x; // 256
    const size_t gbase = (size_t)bh * Sn;

    float fgl[8], igl[8], Fl[8], Gl[8];
    int tbase = tid * 8;
    #pragma unroll
    for (int j = 0; j < 8; j++) {
        int t = tbase + j;
        fgl[j] = fg[((size_t)b*Sn + t)*Hn + h];
        igl[j] = ig[((size_t)b*Sn + t)*Hn + h];
    }
    float F = 0.f, G = -INFINITY;
    #pragma unroll
    for (int j = 0; j < 8; j++) {
        F += fgl[j]; Fl[j] = F;
        G = fmaxf(G, igl[j] - F); Gl[j] = G;
    }
    sF[tid] = F; sG[tid] = G;
    __syncthreads();
    if (tid == 0) {
        float aF = 0.f, aG = -INFINITY;
        for (int i = 0; i < 256; i++) {
            oFp[i] = aF; pGp[i] = aG;
            aG = fmaxf(aG, sG[i] - aF);
            aF += sF[i];
        }
    }
    __syncthreads();
    float oF = oFp[tid], pG = pGp[tid];
    float mp = oF + pG;
    #pragma unroll
    for (int j = 0; j < 8; j++) {
        float Ft = oF + Fl[j];
        float Gt = fmaxf(pG, Gl[j] - oF);
        float m = Ft + Gt;
        fe[gbase + tbase + j] = expf(fgl[j] + mp - m);
        ie[gbase + tbase + j] = expf(igl[j] - m);
        mOut[gbase + tbase + j] = m;
        mp = m;
    }
    __syncthreads();

    float nreg = 0.f;
    for (int t0 = 0; t0 < Sn; t0 += 64) {
        #pragma unroll
        for (int p = 0; p < 4; p++) {
            int idx = tid + 256 * p;            // 1024 float4 slots
            int tt = idx >> 4, j4 = (idx & 15) << 2;
            size_t go = ((size_t)b*Sn + t0 + tt)*Dn + h*DHn + j4;
            *reinterpret_cast<float4*>(&kbuf[tt*68 + j4]) = *reinterpret_cast<const float4*>(k + go);
            *reinterpret_cast<float4*>(&qbuf[tt*68 + j4]) = *reinterpret_cast<const float4*>(q + go);
        }
        if (tid < 64) fes[tid] = fe[gbase + t0 + tid];
        else if (tid < 128) ies[tid-64] = ie[gbase + t0 + tid - 64];
        __syncthreads();
        if (tid < 64) {
            #pragma unroll 4
            for (int tt = 0; tt < 64; tt++) {
                nreg = fes[tt] * nreg + ies[tt] * kbuf[tt*68 + tid];
                kbuf[tt*68 + tid] = nreg;
            }
        }
        __syncthreads();
        if (tid < 64) {
            float den = 0.f;
            #pragma unroll 8
            for (int j = 0; j < 64; j++) den += kbuf[tid*68 + j] * qbuf[tid*68 + j];
            rd[gbase + t0 + tid] = 1.0f / fmaxf(fabsf(den), 1.0f);
        }
        __syncthreads();
    }
}

// 6a) chunk phase A: log-space anchored scaling; S=tril(Q'K'^T), intra=S@V, G=V^T K'.
__global__ void chunkA(float* __restrict__ q, const float* __restrict__ k,
                       const float* __restrict__ v,
                       const float* __restrict__ ig, const float* __restrict__ fg,
                       const float* __restrict__ mArr,
                       float* __restrict__ hintra, float* __restrict__ Gout,
                       float* __restrict__ SC) {
    extern __shared__ float sm[];
    float* sQ = sm;              // 64*68 (later S)
    float* sK = sm + 64*68;
    float* sV = sm + 2*64*68;
    float* sfg = sm + 3*64*68;   // 64
    float* sig_ = sfg + 64;
    float* smv = sig_ + 64;
    float* sFl = smv + 64;
    float* sRow = sFl + 64;
    float* sCol = sRow + 64;
    float* sScal = sCol + 64;    // 4

    int c = blockIdx.x, bh = blockIdx.y;
    int b = bh / Hn, h = bh - b * Hn;
    int t0 = c * 64;
    int tid = threadIdx.x;       // 128
    int lane = tid & 31, w = tid >> 5;
    int gq = lane >> 2, tg = lane & 3;
    size_t gbase = (size_t)bh * Sn + t0;

    if (tid < 64) {
        int t = t0 + tid;
        sfg[tid]  = fg[((size_t)b*Sn + t)*Hn + h];
        sig_[tid] = ig[((size_t)b*Sn + t)*Hn + h];
        smv[tid]  = mArr[gbase + tid];
    }
    __syncthreads();
    if (tid == 0) {
        float Fl = 0.f, AA = -INFINITY;
        for (int i = 0; i < 64; i++) {
            Fl += sfg[i]; sFl[i] = Fl;
            AA = fmaxf(AA, sig_[i] - Fl);
        }
        float mT1 = smv[63];
        bool first = (c == 0);
        float Ac = first ? 0.f : mArr[gbase - 1];
        sScal[0] = first ? 0.f : expf(Ac - AA);              // s_c
        sScal[1] = first ? 0.f : expf(sFl[63] + Ac - mT1);   // PL
        sScal[2] = expf(AA + sFl[63] - mT1);                 // gfac
        sScal[3] = AA;
    }
    __syncthreads();
    if (tid < 64) {
        float AA = sScal[3];
        sRow[tid] = expf(sFl[tid] - smv[tid] + AA);
        sCol[tid] = expf(sig_[tid] - sFl[tid] - AA);
    }
    if (tid >= 64 && tid < 67) SC[(size_t)(bh*NC + c)*4 + (tid - 64)] = sScal[tid - 64];
    __syncthreads();

    {
        int i = tid >> 1, hf = tid & 1;
        size_t ro = ((size_t)b*Sn + t0 + i)*Dn + h*DHn + hf*32;
        float rsc = sRow[i];
        float csc = sCol[i];
        #pragma unroll
        for (int p = 0; p < 8; p++) {
            int j = hf*32 + p*4;
            float4 qv = *reinterpret_cast<const float4*>(q + ro + p*4);
            float4 kv = *reinterpret_cast<const float4*>(k + ro + p*4);
            float4 vv = *reinterpret_cast<const float4*>(v + ro + p*4);
            qv.x *= rsc; qv.y *= rsc; qv.z *= rsc; qv.w *= rsc;
            *reinterpret_cast<float4*>(q + ro + p*4) = qv;    // Q' in place
            sQ[i*68+j+0]=cvt_tf32(qv.x); sQ[i*68+j+1]=cvt_tf32(qv.y);
            sQ[i*68+j+2]=cvt_tf32(qv.z); sQ[i*68+j+3]=cvt_tf32(qv.w);
            sK[i*68+j+0]=cvt_tf32(kv.x*csc); sK[i*68+j+1]=cvt_tf32(kv.y*csc);
            sK[i*68+j+2]=cvt_tf32(kv.z*csc); sK[i*68+j+3]=cvt_tf32(kv.w*csc);
            sV[i*68+j+0]=cvt_tf32(vv.x); sV[i*68+j+1]=cvt_tf32(vv.y);
            sV[i*68+j+2]=cvt_tf32(vv.z); sV[i*68+j+3]=cvt_tf32(vv.w);
        }
    }
    __syncthreads();

    // GEMM1: S = Q' @ K'^T
    float accS[8][4];
    #pragma unroll
    for (int nt = 0; nt < 8; nt++)
        #pragma unroll
        for (int x = 0; x < 4; x++) accS[nt][x] = 0.f;
    int m0 = w * 16;
    #pragma unroll
    for (int kk = 0; kk < 64; kk += 8) {
        uint32_t af[4];
        af[0] = __float_as_uint(sQ[(m0+gq)*68 + kk+tg]);
        af[1] = __float_as_uint(sQ[(m0+gq+8)*68 + kk+tg]);
        af[2] = __float_as_uint(sQ[(m0+gq)*68 + kk+4+tg]);
        af[3] = __float_as_uint(sQ[(m0+gq+8)*68 + kk+4+tg]);
        #pragma unroll
        for (int nt = 0; nt < 8; nt++) {
            uint32_t bf[2];
            bf[0] = __float_as_uint(sK[(nt*8+gq)*68 + kk+tg]);
            bf[1] = __float_as_uint(sK[(nt*8+gq)*68 + kk+4+tg]);
            mma_tf32(accS[nt], af, bf);
        }
    }
    __syncthreads();
    #pragma unroll
    for (int nt = 0; nt < 8; nt++) {
        int r0 = m0 + gq, r1 = r0 + 8;
        int c0 = nt*8 + tg*2, c1 = c0 + 1;
        sQ[r0*68 + c0] = (c0 <= r0) ? cvt_tf32(accS[nt][0]) : 0.f;
        sQ[r0*68 + c1] = (c1 <= r0) ? cvt_tf32(accS[nt][1]) : 0.f;
        sQ[r1*68 + c0] = (c0 <= r1) ? cvt_tf32(accS[nt][2]) : 0.f;
        sQ[r1*68 + c1] = (c1 <= r1) ? cvt_tf32(accS[nt][3]) : 0.f;
    }
    __syncthreads();

    // GEMM2: intra = S @ V
    float accI[8][4];
    #pragma unroll
    for (int nt = 0; nt < 8; nt++)
        #pragma unroll
        for (int x = 0; x < 4; x++) accI[nt][x] = 0.f;
    #pragma unroll
    for (int kk = 0; kk < 64; kk += 8) {
        uint32_t af[4];
        af[0] = __float_as_uint(sQ[(m0+gq)*68 + kk+tg]);
        af[1] = __float_as_uint(sQ[(m0+gq+8)*68 + kk+tg]);
        af[2] = __float_as_uint(sQ[(m0+gq)*68 + kk+4+tg]);
        af[3] = __float_as_uint(sQ[(m0+gq+8)*68 + kk+4+tg]);
        #pragma unroll
        for (int nt = 0; nt < 8; nt++) {
            uint32_t bf[2];
            bf[0] = __float_as_uint(sV[(kk+tg)*68 + nt*8+gq]);
            bf[1] = __float_as_uint(sV[(kk+4+tg)*68 + nt*8+gq]);
            mma_tf32(accI[nt], af, bf);
        }
    }
    #pragma unroll
    for (int nt = 0; nt < 8; nt++) {
        int r0 = m0 + gq, r1 = r0 + 8;
        int c0 = nt*8 + tg*2;
        size_t o0 = (gbase + r0) * DHn + c0;
        size_t o1 = (gbase + r1) * DHn + c0;
        *reinterpret_cast<float2*>(hintra + o0) = make_float2(accI[nt][0], accI[nt][1]);
        *reinterpret_cast<float2*>(hintra + o1) = make_float2(accI[nt][2], accI[nt][3]);
    }

    // GEMM3: G = V^T @ K'
    float accG[8][4];
    #pragma unroll
    for (int nt = 0; nt < 8; nt++)
        #pragma unroll
        for (int x = 0; x < 4; x++) accG[nt][x] = 0.f;
    #pragma unroll
    for (int kk = 0; kk < 64; kk += 8) {
        uint32_t af[4];
        af[0] = __float_as_uint(sV[(kk+tg)*68 + m0+gq]);
        af[1] = __float_as_uint(sV[(kk+tg)*68 + m0+gq+8]);
        af[2] = __float_as_uint(sV[(kk+4+tg)*68 + m0+gq]);
        af[3] = __float_as_uint(sV[(kk+4+tg)*68 + m0+gq+8]);
        #pragma unroll
        for (int nt = 0; nt < 8; nt++) {
            uint32_t bf[2];
            bf[0] = __float_as_uint(sK[(kk+tg)*68 + nt*8+gq]);
            bf[1] = __float_as_uint(sK[(kk+4+tg)*68 + nt*8+gq]);
            mma_tf32(accG[nt], af, bf);
        }
    }
    size_t Gb = ((size_t)bh*NC + c) * DHn * DHn;
    #pragma unroll
    for (int nt = 0; nt < 8; nt++) {
        int r0 = m0 + gq, r1 = r0 + 8;
        int c0 = nt*8 + tg*2;
        *reinterpret_cast<float2*>(Gout + Gb + (size_t)r0*DHn + c0) = make_float2(accG[nt][0], accG[nt][1]);
        *reinterpret_cast<float2*>(Gout + Gb + (size_t)r1*DHn + c0) = make_float2(accG[nt][2], accG[nt][3]);
    }
}

// 6b) phase B: serial over chunks, 2 blocks per (b,h) split on v (C rows).
//     Ninter = s_c*(Q' @ C^T); h=(intra+Ninter)*rd; C = PL*C + gfac*G.
__global__ void chunkB(const float* __restrict__ qp, const float* __restrict__ Gin,
                       const float* __restrict__ SC, const float* __restrict__ rd,
                       float* __restrict__ hio) {
    __shared__ float sC[32*68];
    __shared__ float sQ[64*68];
    int bh = blockIdx.x >> 1;
    int half = blockIdx.x & 1;
    int b = bh / Hn, h = bh - b * Hn;
    int tid = threadIdx.x;  // 128
    int lane = tid & 31, w = tid >> 5;
    int gq = lane >> 2, tg = lane & 3;
    int m0 = w * 16;
    int rq = tid >> 1, hfq = tid & 1;   // Q staging
    int rc = tid >> 2, qf = tid & 3;    // C ownership: row rc (0..31), cols qf*16..

    float Creg[16];
    #pragma unroll
    for (int j = 0; j < 16; j++) Creg[j] = 0.f;
    for (int idx = tid; idx < 32*68; idx += 128) sC[idx] = 0.f;
    __syncthreads();

    for (int c = 0; c < NC; c++) {
        int t0 = c * 64;
        float s_c  = SC[(size_t)(bh*NC + c)*4 + 0];
        float PLc  = SC[(size_t)(bh*NC + c)*4 + 1];
        float gfac = SC[(size_t)(bh*NC + c)*4 + 2];
        {
            size_t ro = ((size_t)b*Sn + t0 + rq)*Dn + h*DHn + hfq*32;
            #pragma unroll
            for (int p = 0; p < 8; p++) {
                float4 qv = *reinterpret_cast<const float4*>(qp + ro + p*4);
                int j = hfq*32 + p*4;
                sQ[rq*68+j+0]=cvt_tf32(qv.x); sQ[rq*68+j+1]=cvt_tf32(qv.y);
                sQ[rq*68+j+2]=cvt_tf32(qv.z); sQ[rq*68+j+3]=cvt_tf32(qv.w);
            }
        }
        __syncthreads();
        // Ninter(local cols) = Q'(64x64) @ C^T(32x64)
        float acc[4][4];
        #pragma unroll
        for (int nt = 0; nt < 4; nt++)
            #pragma unroll
            for (int x = 0; x < 4; x++) acc[nt][x] = 0.f;
        #pragma unroll
        for (int kk = 0; kk < 64; kk += 8) {
            uint32_t af[4];
            af[0] = __float_as_uint(sQ[(m0+gq)*68 + kk+tg]);
            af[1] = __float_as_uint(sQ[(m0+gq+8)*68 + kk+tg]);
            af[2] = __float_as_uint(sQ[(m0+gq)*68 + kk+4+tg]);
            af[3] = __float_as_uint(sQ[(m0+gq+8)*68 + kk+4+tg]);
            #pragma unroll
            for (int nt = 0; nt < 4; nt++) {
                uint32_t bf[2];
                bf[0] = __float_as_uint(sC[(nt*8+gq)*68 + kk+tg]);
                bf[1] = __float_as_uint(sC[(nt*8+gq)*68 + kk+4+tg]);
                mma_tf32(acc[nt], af, bf);
            }
        }
        #pragma unroll
        for (int nt = 0; nt < 4; nt++) {
            int r0 = m0 + gq, r1 = r0 + 8;
            int c0 = half*32 + nt*8 + tg*2;
            size_t u0 = (size_t)bh*Sn + t0 + r0;
            size_t u1 = (size_t)bh*Sn + t0 + r1;
            float rd0 = rd[u0], rd1 = rd[u1];
            float2 i0 = *reinterpret_cast<const float2*>(hio + u0*DHn + c0);
            float2 i1 = *reinterpret_cast<const float2*>(hio + u1*DHn + c0);
            *reinterpret_cast<float2*>(hio + u0*DHn + c0) =
                make_float2((i0.x + s_c*acc[nt][0]) * rd0, (i0.y + s_c*acc[nt][1]) * rd0);
            *reinterpret_cast<float2*>(hio + u1*DHn + c0) =
                make_float2((i1.x + s_c*acc[nt][2]) * rd1, (i1.y + s_c*acc[nt][3]) * rd1);
        }
        __syncthreads();
        size_t Gb = ((size_t)bh*NC + c) * DHn * DHn + (size_t)(half*32 + rc)*DHn + qf*16;
        #pragma unroll
        for (int p = 0; p < 4; p++) {
            float4 gv = *reinterpret_cast<const float4*>(Gin + Gb + p*4);
            int j = p*4;
            Creg[j+0] = PLc * Creg[j+0] + gfac * gv.x;
            Creg[j+1] = PLc * Creg[j+1] + gfac * gv.y;
            Creg[j+2] = PLc * Creg[j+2] + gfac * gv.z;
            Creg[j+3] = PLc * Creg[j+3] + gfac * gv.w;
            int cc = qf*16 + j;
            sC[rc*68+cc+0]=cvt_tf32(Creg[j+0]); sC[rc*68+cc+1]=cvt_tf32(Creg[j+1]);
            sC[rc*68+cc+2]=cvt_tf32(Creg[j+2]); sC[rc*68+cc+3]=cvt_tf32(Creg[j+3]);
        }
        __syncthreads();
    }
}

// 7) GroupNorm + unflip + multiply by LN out
__global__ void gnprod_kernel(const float* __restrict__ hin,
                              const float* __restrict__ gn_g, const float* __restrict__ gn_b,
                              const float* __restrict__ outln,
                              const int* __restrict__ flipPtr,
                              float* __restrict__ prod) {
    int w = threadIdx.x >> 5, lane = threadIdx.x & 31;
    int u = blockIdx.x * 8 + w;
    int b = u / (Hn * Sn);
    int rem = u - b * (Hn * Sn);
    int h = rem / Sn, t = rem - h * Sn;
    float v0 = hin[(size_t)u*DHn + lane];
    float v1 = hin[(size_t)u*DHn + 32 + lane];
    float mu = warp_sum(v0 + v1) * (1.0f / DHn);
    float x0 = v0 - mu, x1 = v1 - mu;
    float rs = rsqrtf(warp_sum(x0*x0 + x1*x1) * (1.0f / DHn) + 1e-5f);
    int d0 = h*DHn + lane, d1 = d0 + 32;
    float hn0 = x0*rs*gn_g[d0] + gn_b[d0];
    float hn1 = x1*rs*gn_g[d1] + gn_b[d1];
    int s = (*flipPtr) ? (Sn - 1 - t) : t;
    size_t row = ((size_t)b*Sn + s) * Dn;
    prod[row + d0] = hn0 * outln[row + d0];
    prod[row + d1] = hn1 * outln[row + d1];
}

extern "C" void kernel_launch(void* const* d_in, const int* in_sizes, int n_in,
                              void* d_out, int out_size) {
    const float* x    = (const float*)d_in[0];
    const float* ln_g = (const float*)d_in[1];
    const float* ln_b = (const float*)d_in[2];
    const float* W2   = (const float*)d_in[5];
    const float* b2   = (const float*)d_in[6];
    const float* W3   = (const float*)d_in[7];
    const float* b3   = (const float*)d_in[8];
    const float* cw   = (const float*)d_in[9];
    const float* cb   = (const float*)d_in[10];
    const float* Wq   = (const float*)d_in[11];
    const float* bq   = (const float*)d_in[12];
    const float* Wk   = (const float*)d_in[13];
    const float* bk   = (const float*)d_in[14];
    const float* Wv   = (const float*)d_in[15];
    const float* bv   = (const float*)d_in[16];
    const float* Wi   = (const float*)d_in[17];
    const float* bi   = (const float*)d_in[18];
    const float* Wf   = (const float*)d_in[19];
    const float* bf   = (const float*)d_in[20];
    const float* gn_g = (const float*)d_in[21];
    const float* gn_b = (const float*)d_in[22];
    const int*   flip = (const int*)d_in[23];
    float* out = (float*)d_out;

    float *p_out, *p_left, *p_xc, *p_q, *p_k, *p_v, *p_ig, *p_fg,
          *p_fe, *p_ie, *p_m, *p_rd, *p_h, *p_G, *p_SC, *p_prod;
    cudaGetSymbolAddress((void**)&p_out,  g_out);
    cudaGetSymbolAddress((void**)&p_left, g_left);
    cudaGetSymbolAddress((void**)&p_xc,   g_xc);
    cudaGetSymbolAddress((void**)&p_q,    g_q);
    cudaGetSymbolAddress((void**)&p_k,    g_k);
    cudaGetSymbolAddress((void**)&p_v,    g_v);
    cudaGetSymbolAddress((void**)&p_ig,   g_ig);
    cudaGetSymbolAddress((void**)&p_fg,   g_fg);
    cudaGetSymbolAddress((void**)&p_fe,   g_fe);
    cudaGetSymbolAddress((void**)&p_ie,   g_ie);
    cudaGetSymbolAddress((void**)&p_m,    g_m);
    cudaGetSymbolAddress((void**)&p_rd,   g_rd);
    cudaGetSymbolAddress((void**)&p_h,    g_h);
    cudaGetSymbolAddress((void**)&p_G,    g_G);
    cudaGetSymbolAddress((void**)&p_SC,   g_SC);
    cudaGetSymbolAddress((void**)&p_prod, g_prod);

    cudaError_t attr_ok = cudaFuncSetAttribute(
        chunkA, cudaFuncAttributeMaxDynamicSharedMemorySize, 54560);
    (void)attr_ok;

    dim3 ggrid(BSn / 128, Dn / 64);

    ln_kernel<<<BSn / 4, 128>>>(x, ln_g, ln_b, p_out);
    gemm_tf32<<<ggrid, 256>>>(p_out, W2, b2, p_left, nullptr, 1.0f, flip);
    conv_kernel<<<BSn, 128>>>(p_left, cw, cb, p_xc);
    gemm_tf32<<<ggrid, 256>>>(p_xc,   Wq, bq, p_q, nullptr, 1.0f,   nullptr);
    gemm_tf32<<<ggrid, 256>>>(p_xc,   Wk, bk, p_k, nullptr, 0.125f, nullptr);
    gemm_tf32<<<ggrid, 256>>>(p_left, Wv, bv, p_v, nullptr, 1.0f,   nullptr);
    igfg_kernel<<<BSn / 8, 256>>>(p_left, Wi, bi, Wf, bf, p_ig, p_fg);
    gates_kernel<<<BHn, 256>>>(p_ig, p_fg, p_k, p_q, p_fe, p_ie, p_m, p_rd);
    chunkA<<<dim3(NC, BHn), 128, 54560>>>(p_q, p_k, p_v, p_ig, p_fg, p_m, p_h, p_G, p_SC);
    chunkB<<<BHn * 2, 128>>>(p_q, p_G, p_SC, p_rd, p_h);
    gnprod_kernel<<<(BHn * Sn) / 8, 256>>>(p_h, gn_g, gn_b, p_out, flip, p_prod);
    gemm_tf32<<<ggrid, 256>>>(p_prod, W3, b3, out, x, 1.0f, nullptr);
}